// round 10
// baseline (speedup 1.0000x reference)
#include <cuda_runtime.h>
#include <cuda_bf16.h>
#include <cuda_fp16.h>
#include <math.h>
#include <stdint.h>

// Problem constants
#define Bn   64
#define Ln   512
#define En   300
#define Vv   50000
#define Pn   200
#define Dn   2800          // P * 2 * M
#define Hn   100
#define Mtot (Bn * Ln)     // 32768
#define NEG  (-100.0f)
#define NINF (-1.0e30f)

// GEMM: main term bf16 (K=320), correction terms int8 (K=640 = hi|lo halves)
#define Kp    320
#define KI8   640
#define Np    2816
#define TM    128
#define TN    128
#define NKT   20                 // chunks: 0-9 int8 (64 s8), 10-19 bf16 (32 bf16)
#define ROWB  80u                // padded smem row stride (64B data + 16B pad)
#define ASZ   (128u * ROWB)      // 10240
#define STAGE (2u * ASZ)         // 20480
#define NSTG  3
#define SMEM_DYN (NSTG * STAGE)  // 61440

// int8 quantization scales
#define SAq    (6.0f / 127.0f)
#define SBq    (1.0f / 127.0f)
#define SCALEi (6.0f / (127.0f * 127.0f * 256.0f))

// Scan split config
#define NCH   4
#define CL    (Ln / NCH)         // 128

// Scratch (static device globals — no dynamic allocation)
__device__ float                        g_scores[Bn * Pn];
__device__ __align__(256) __half        g_tsu[(size_t)Mtot * Np];  // [uid][n] fp16
__device__ __align__(256) float         g_part[(size_t)Bn * Pn * NCH * 64];
__device__ __align__(256) __nv_bfloat16 g_A2[(size_t)Mtot * Kp];   // hi
__device__ __align__(256) __nv_bfloat16 g_B2[(size_t)Np * Kp];     // hi
__device__ __align__(256) int8_t        g_A8[(size_t)Mtot * KI8];  // [hiq|loq]
__device__ __align__(256) int8_t        g_B8[(size_t)Np * KI8];    // [loq|hiq]
__device__ int g_flag[Vv];
__device__ int g_tok[Mtot];
__device__ int g_uid[Mtot];
__device__ int g_count;

// ---------------------------------------------------------------------------
// PTX helpers (baseline PTX only)
// ---------------------------------------------------------------------------
__device__ __forceinline__ uint32_t s2u(const void* p) {
    uint32_t a;
    asm("{ .reg .u64 t; cvta.to.shared.u64 t, %1; cvt.u32.u64 %0, t; }"
        : "=r"(a) : "l"(p));
    return a;
}

#define CP_ASYNC16(dst, src) \
    asm volatile("cp.async.cg.shared.global [%0], [%1], 16;" :: "r"(dst), "l"(src) : "memory")
#define CP_COMMIT() asm volatile("cp.async.commit_group;" ::: "memory")
#define CP_WAIT(n)  asm volatile("cp.async.wait_group %0;" :: "n"(n) : "memory")

#define LDSM_X4(r, addr)                                                        \
    asm volatile("ldmatrix.sync.aligned.m8n8.x4.shared.b16 {%0,%1,%2,%3}, [%4];" \
        : "=r"((r)[0]), "=r"((r)[1]), "=r"((r)[2]), "=r"((r)[3]) : "r"(addr))

#define LDSM_X4_B(r0, r1, r2, r3, addr)                                         \
    asm volatile("ldmatrix.sync.aligned.m8n8.x4.shared.b16 {%0,%1,%2,%3}, [%4];" \
        : "=r"(r0), "=r"(r1), "=r"(r2), "=r"(r3) : "r"(addr))

#define MMA_BF16(d, a, b)                                                       \
    asm volatile("mma.sync.aligned.m16n8k16.row.col.f32.bf16.bf16.f32 "         \
        "{%0,%1,%2,%3}, {%4,%5,%6,%7}, {%8,%9}, {%0,%1,%2,%3};"                 \
        : "+f"((d)[0]), "+f"((d)[1]), "+f"((d)[2]), "+f"((d)[3])                \
        : "r"((a)[0]), "r"((a)[1]), "r"((a)[2]), "r"((a)[3]),                   \
          "r"((b)[0]), "r"((b)[1]))

#define MMA_S8(d, a, b)                                                         \
    asm volatile("mma.sync.aligned.m16n8k32.row.col.s32.s8.s8.s32 "             \
        "{%0,%1,%2,%3}, {%4,%5,%6,%7}, {%8,%9}, {%0,%1,%2,%3};"                 \
        : "+r"((d)[0]), "+r"((d)[1]), "+r"((d)[2]), "+r"((d)[3])                \
        : "r"((a)[0]), "r"((a)[1]), "r"((a)[2]), "r"((a)[3]),                   \
          "r"((b)[0]), "r"((b)[1]))

__device__ __forceinline__ int8_t q8(float x, float inv_s) {
    int v = __float2int_rn(x * inv_s);
    v = max(-127, min(127, v));
    return (int8_t)v;
}

// ---------------------------------------------------------------------------
// Dedup: flag -> prefix scan (deterministic) -> uid maps
// ---------------------------------------------------------------------------
__global__ void dedup_clear_kernel() {
    const int i = blockIdx.x * blockDim.x + threadIdx.x;
    if (i < Vv) g_flag[i] = 0;
}
__global__ void dedup_mark_kernel(const int* __restrict__ docs) {
    const int m = blockIdx.x * blockDim.x + threadIdx.x;
    if (m < Mtot) g_flag[docs[m]] = 1;
}
__global__ void __launch_bounds__(1024) dedup_scan_kernel() {
    __shared__ int ss[1024];
    const int tid = threadIdx.x;
    const int CHUNK = (Vv + 1023) / 1024;
    const int base = tid * CHUNK;
    int s = 0;
    for (int i = 0; i < CHUNK; i++) {
        const int v = base + i;
        if (v < Vv) s += g_flag[v];
    }
    ss[tid] = s;
    __syncthreads();
    for (int off = 1; off < 1024; off <<= 1) {
        int v = (tid >= off) ? ss[tid - off] : 0;
        __syncthreads();
        ss[tid] += v;
        __syncthreads();
    }
    int run = (tid == 0) ? 0 : ss[tid - 1];
    if (tid == 1023) g_count = ss[1023];
    for (int i = 0; i < CHUNK; i++) {
        const int v = base + i;
        if (v < Vv && g_flag[v]) {
            g_tok[run] = v;
            g_flag[v] = run + 1;
            run++;
        }
    }
}
__global__ void dedup_uid_kernel(const int* __restrict__ docs) {
    const int m = blockIdx.x * blockDim.x + threadIdx.x;
    if (m < Mtot) g_uid[m] = g_flag[docs[m]] - 1;
}

// ---------------------------------------------------------------------------
// Conversion: bf16 hi + int8 quantized hi/lo
// ---------------------------------------------------------------------------
__global__ void conv_emb_kernel(const float* __restrict__ emb)
{
    const int u = blockIdx.x;
    if (u >= g_count) return;
    const int k = threadIdx.x;          // 0..319
    const int tok = g_tok[u];
    float x = (k < En) ? emb[(size_t)tok * En + k] : 0.0f;
    __nv_bfloat16 hi = __float2bfloat16(x);
    float hif = __bfloat162float(hi);
    float lo  = x - hif;
    g_A2[(size_t)u * Kp + k] = hi;
    g_A8[(size_t)u * KI8 + k]      = q8(hif, 1.0f / SAq);            // hiq
    g_A8[(size_t)u * KI8 + Kp + k] = q8(lo,  256.0f / SAq);          // loq
}

__global__ void conv_diag_kernel(const float* __restrict__ diags)
{
    const int d = blockIdx.x;           // 0..2815
    const int k = threadIdx.x;
    float x = (d < Dn && k < En) ? diags[(size_t)d * En + k] : 0.0f;
    __nv_bfloat16 hi = __float2bfloat16(x);
    float hif = __bfloat162float(hi);
    float lo  = x - hif;
    g_B2[(size_t)d * Kp + k] = hi;
    g_B8[(size_t)d * KI8 + k]      = q8(lo,  256.0f / SBq);          // loq
    g_B8[(size_t)d * KI8 + Kp + k] = q8(hif, 1.0f / SBq);            // hiq
}

// ---------------------------------------------------------------------------
// Kernel 1: mixed int8/bf16 HMMA GEMM over uid rows.
// Phase A (chunks 0-9):  s8 m16n8k32 over K=640  -> cross terms, s32 accum
// Phase B (chunks 10-19): bf16 m16n8k16 over K=320 -> main term, f32 accum
// ts_u[u,n] = hh + SCALEi*ci + bias[n], stored fp16.
// ---------------------------------------------------------------------------
__global__ void __launch_bounds__(256, 2)
gemm_hmma_kernel(const float* __restrict__ bias)
{
    const int m0 = blockIdx.y * TM;
    const int cnt = g_count;
    if (m0 >= cnt) return;

    extern __shared__ char smem[];
    const uint32_t sbase = s2u(smem);

    const int tid  = threadIdx.x;
    const int wid  = tid >> 5;
    const int lane = tid & 31;
    const int wm   = wid & 3;
    const int wn   = wid >> 2;
    const int n0   = blockIdx.x * TN;

    // identical fragment addressing for bf16-k16 and s8-k32 (32B per ks)
    const uint32_t aoff = (uint32_t)((((lane >> 3) & 1) * 8 + (lane & 7)) * ROWB
                                     + (lane >> 4) * 16);
    const uint32_t boff = (uint32_t)(((lane >> 4) * 8 + (lane & 7)) * ROWB
                                     + ((lane >> 3) & 1) * 16);

    const int cr0 = tid >> 2;            // rows 0..63 (+64)
    const int cg  = (tid & 3) * 16;      // byte granule within 64B row

    auto load_stage = [&](int buf, int kt) {
        const uint32_t sb = sbase + (uint32_t)buf * STAGE;
        if (kt < 10) {                   // int8: 64 s8 per row
            const int k0 = kt * 64 + cg;
            #pragma unroll
            for (int u = 0; u < 2; u++) {
                const int r = cr0 + u * 64;
                CP_ASYNC16(sb + (uint32_t)r * ROWB + (uint32_t)cg,
                           g_A8 + (size_t)(m0 + r) * KI8 + k0);
                CP_ASYNC16(sb + ASZ + (uint32_t)r * ROWB + (uint32_t)cg,
                           g_B8 + (size_t)(n0 + r) * KI8 + k0);
            }
        } else {                         // bf16: 32 bf16 = 64B per row
            const int ck = kt - 10;
            const int k0 = ck * 32 + (cg >> 1);           // bf16 elements
            const bool used = (ck != 9) || (cg < 32);     // k 304-319 zero
            if (used) {
                #pragma unroll
                for (int u = 0; u < 2; u++) {
                    const int r = cr0 + u * 64;
                    CP_ASYNC16(sb + (uint32_t)r * ROWB + (uint32_t)cg,
                               g_A2 + (size_t)(m0 + r) * Kp + k0);
                    CP_ASYNC16(sb + ASZ + (uint32_t)r * ROWB + (uint32_t)cg,
                               g_B2 + (size_t)(n0 + r) * Kp + k0);
                }
            }
        }
        CP_COMMIT();
    };

    // ---- phase A: int8 cross terms ----
    int ci[2][8][4];
    #pragma unroll
    for (int i = 0; i < 2; i++)
        #pragma unroll
        for (int j = 0; j < 8; j++)
            #pragma unroll
            for (int q = 0; q < 4; q++) ci[i][j][q] = 0;

    load_stage(0, 0);
    load_stage(1, 1);

    for (int kt = 0; kt < 10; kt++) {
        CP_WAIT(1);
        __syncthreads();
        load_stage((kt + 2) % NSTG, kt + 2);

        const uint32_t sA = sbase + (uint32_t)(kt % NSTG) * STAGE;
        const uint32_t sB = sA + ASZ;
        #pragma unroll
        for (int ks = 0; ks < 2; ks++) {
            uint32_t a[2][4], bfr[8][2];
            #pragma unroll
            for (int i = 0; i < 2; i++)
                LDSM_X4(a[i], sA + (uint32_t)((wm * 32 + i * 16) * ROWB) + (uint32_t)(ks * 32) + aoff);
            #pragma unroll
            for (int j2 = 0; j2 < 4; j2++)
                LDSM_X4_B(bfr[j2 * 2][0], bfr[j2 * 2][1],
                          bfr[j2 * 2 + 1][0], bfr[j2 * 2 + 1][1],
                          sB + (uint32_t)((wn * 64 + j2 * 16) * ROWB) + (uint32_t)(ks * 32) + boff);
            #pragma unroll
            for (int i = 0; i < 2; i++)
                #pragma unroll
                for (int j = 0; j < 8; j++)
                    MMA_S8(ci[i][j], a[i], bfr[j]);
        }
    }

    // ---- convert: c = ci * SCALEi (ci dead afterwards) ----
    float c[2][8][4];
    #pragma unroll
    for (int i = 0; i < 2; i++)
        #pragma unroll
        for (int j = 0; j < 8; j++)
            #pragma unroll
            for (int q = 0; q < 4; q++) c[i][j][q] = (float)ci[i][j][q] * SCALEi;

    // ---- phase B: bf16 main term ----
    for (int kt = 10; kt < NKT; kt++) {
        if (kt < NKT - 1) CP_WAIT(1);
        else              CP_WAIT(0);
        __syncthreads();
        if (kt + 2 < NKT) load_stage((kt + 2) % NSTG, kt + 2);

        const uint32_t sA = sbase + (uint32_t)(kt % NSTG) * STAGE;
        const uint32_t sB = sA + ASZ;
        const int nks = (kt != NKT - 1) ? 2 : 1;      // tail: k 304-319 zero
        for (int ks = 0; ks < nks; ks++) {
            uint32_t a[2][4], bfr[8][2];
            #pragma unroll
            for (int i = 0; i < 2; i++)
                LDSM_X4(a[i], sA + (uint32_t)((wm * 32 + i * 16) * ROWB) + (uint32_t)(ks * 32) + aoff);
            #pragma unroll
            for (int j2 = 0; j2 < 4; j2++)
                LDSM_X4_B(bfr[j2 * 2][0], bfr[j2 * 2][1],
                          bfr[j2 * 2 + 1][0], bfr[j2 * 2 + 1][1],
                          sB + (uint32_t)((wn * 64 + j2 * 16) * ROWB) + (uint32_t)(ks * 32) + boff);
            #pragma unroll
            for (int i = 0; i < 2; i++)
                #pragma unroll
                for (int j = 0; j < 8; j++)
                    MMA_BF16(c[i][j], a[i], bfr[j]);
        }
    }

    // ---- epilogue: fp16 [uid][n] store with bias ----
    const int gid = lane >> 2;
    const int tig = lane & 3;
    #pragma unroll
    for (int i = 0; i < 2; i++) {
        const int r0 = m0 + wm * 32 + i * 16 + gid;
        #pragma unroll
        for (int j = 0; j < 8; j++) {
            const int n = n0 + wn * 64 + j * 8 + tig * 2;
            const float bx = __ldg(bias + (n < Dn ? n : 0));
            const float by = __ldg(bias + (n + 1 < Dn ? n + 1 : 0));
            #pragma unroll
            for (int h = 0; h < 2; h++) {
                const int m = r0 + h * 8;
                if (m < cnt) {
                    __half2 v = __floats2half2_rn(c[i][j][h * 2] + bx,
                                                  c[i][j][h * 2 + 1] + by);
                    *reinterpret_cast<__half2*>(g_tsu + (size_t)m * Np + n) = v;
                }
            }
        }
    }
}

// ---------------------------------------------------------------------------
// Kernel 2a: chunked max-plus scan; each ts row read once per (b,ch) block.
// Block = (batch, chunk); 200 threads = patterns. Triangular basis.
// ---------------------------------------------------------------------------
__global__ void __launch_bounds__(256)
scan_part_kernel(const float* __restrict__ epsilon)
{
    const int b   = blockIdx.x;
    const int ch  = blockIdx.y;
    const int tid = threadIdx.x;

    __shared__ int uids[CL];
    for (int i = tid; i < CL; i += 256)
        uids[i] = g_uid[b * Ln + ch * CL + i];
    __syncthreads();
    if (tid >= Pn) return;
    const int p = tid;

    float e[6];
    #pragma unroll
    for (int j = 0; j < 6; j++) e[j] = __ldg(epsilon + p * 6 + j);

    float h[8][7];
    #pragma unroll
    for (int j = 0; j < 8; j++)
        #pragma unroll
        for (int i = 0; i < 7; i++) h[j][i] = NINF;
    #pragma unroll
    for (int j = 0; j < 7; j++) h[j][j] = 0.0f;
    float smax[8];
    #pragma unroll
    for (int j = 0; j < 8; j++) smax[j] = NINF;

    const int poff7 = p * 7;   // half2 units

    float2 nxv[7];
    {
        const __half2* r = reinterpret_cast<const __half2*>(
            g_tsu + (size_t)uids[0] * Np) + poff7;
        #pragma unroll
        for (int q = 0; q < 7; q++) nxv[q] = __half22float2(r[q]);
    }

    for (int l = 0; l < CL; l++) {
        float xv[14];
        #pragma unroll
        for (int q = 0; q < 7; q++) { xv[2 * q] = nxv[q].x; xv[2 * q + 1] = nxv[q].y; }
        if (l + 1 < CL) {
            const __half2* r = reinterpret_cast<const __half2*>(
                g_tsu + (size_t)uids[l + 1] * Np) + poff7;
            #pragma unroll
            for (int q = 0; q < 7; q++) nxv[q] = __half22float2(r[q]);
        }

        #pragma unroll
        for (int j = 0; j < 7; j++) {
            float nh[7];
            float aeprev = h[j][j];
            nh[j] = aeprev + xv[j];
            #pragma unroll
            for (int m = j + 1; m < 7; m++) {
                const float aem = fmaxf(h[j][m], h[j][m - 1] + e[m - 1]);
                nh[m] = fmaxf(aeprev + xv[7 + m - 1], aem + xv[m]);
                aeprev = aem;
            }
            smax[j] = fmaxf(smax[j], nh[6]);
            #pragma unroll
            for (int m = j; m < 7; m++) h[j][m] = nh[m];
        }
        {
            float ae[7];
            ae[0] = fmaxf(h[7][0], NEG);
            #pragma unroll
            for (int m = 1; m < 7; m++) ae[m] = fmaxf(h[7][m], h[7][m - 1] + e[m - 1]);
            float nh[7];
            nh[0] = fmaxf(0.0f, ae[0] + xv[0]);
            #pragma unroll
            for (int m = 1; m < 7; m++)
                nh[m] = fmaxf(ae[m - 1] + xv[7 + m - 1], ae[m] + xv[m]);
            smax[7] = fmaxf(smax[7], nh[6]);
            #pragma unroll
            for (int m = 0; m < 7; m++) h[7][m] = nh[m];
        }
    }

    float* slot = g_part + ((size_t)(b * Pn + p) * NCH + ch) * 64;
    #pragma unroll
    for (int j = 0; j < 7; j++)
        #pragma unroll
        for (int i = 0; i < 7; i++) slot[j * 7 + i] = (i >= j) ? h[j][i] : NINF;
    #pragma unroll
    for (int i = 0; i < 7; i++) slot[49 + i] = h[7][i];
    #pragma unroll
    for (int j = 0; j < 8; j++) slot[56 + j] = smax[j];
}

// ---------------------------------------------------------------------------
// Kernel 2b: combine the NCH chunk transforms per chain.
// ---------------------------------------------------------------------------
__global__ void scan_combine_kernel()
{
    const int bp = blockIdx.x * blockDim.x + threadIdx.x;
    if (bp >= Bn * Pn) return;

    float h[7];
    h[0] = 0.0f;
    #pragma unroll
    for (int i = 1; i < 7; i++) h[i] = NEG;
    float s = NEG;

    #pragma unroll 1
    for (int c = 0; c < NCH; c++) {
        const float* sl = g_part + ((size_t)bp * NCH + c) * 64;
        float ns = fmaxf(s, sl[63]);
        #pragma unroll
        for (int j = 0; j < 7; j++) ns = fmaxf(ns, sl[56 + j] + h[j]);
        float nh[7];
        #pragma unroll
        for (int i = 0; i < 7; i++) {
            float v = sl[49 + i];
            #pragma unroll
            for (int j = 0; j < 7; j++) v = fmaxf(v, sl[j * 7 + i] + h[j]);
            nh[i] = v;
        }
        #pragma unroll
        for (int i = 0; i < 7; i++) h[i] = nh[i];
        s = ns;
    }
    g_scores[bp] = s;
}

// ---------------------------------------------------------------------------
// Kernel 3: MLP + log_softmax. One block per batch row.
// ---------------------------------------------------------------------------
__global__ void mlp_kernel(const float* __restrict__ w1, const float* __restrict__ b1,
                           const float* __restrict__ w2, const float* __restrict__ b2,
                           const float* __restrict__ w3, const float* __restrict__ b3,
                           float* __restrict__ out)
{
    const int b = blockIdx.x;
    const int tid = threadIdx.x;
    __shared__ float sc[Pn];
    __shared__ float h1[Hn];
    __shared__ float h2[Hn];

    for (int i = tid; i < Pn; i += blockDim.x) sc[i] = g_scores[b * Pn + i];
    __syncthreads();

    if (tid < Hn) {
        float acc = b1[tid];
        #pragma unroll 4
        for (int p = 0; p < Pn; p++) acc = fmaf(sc[p], w1[p * Hn + tid], acc);
        h1[tid] = fmaxf(acc, 0.f);
    }
    __syncthreads();

    if (tid < Hn) {
        float acc = b2[tid];
        #pragma unroll 4
        for (int j = 0; j < Hn; j++) acc = fmaf(h1[j], w2[j * Hn + tid], acc);
        h2[tid] = fmaxf(acc, 0.f);
    }
    __syncthreads();

    if (tid == 0) {
        float l0 = b3[0], l1 = b3[1];
        for (int j = 0; j < Hn; j++) {
            l0 = fmaf(h2[j], w3[j * 2 + 0], l0);
            l1 = fmaf(h2[j], w3[j * 2 + 1], l1);
        }
        float mx  = fmaxf(l0, l1);
        float lse = mx + logf(expf(l0 - mx) + expf(l1 - mx));
        out[b * 2 + 0] = l0 - lse;
        out[b * 2 + 1] = l1 - lse;
    }
}

// ---------------------------------------------------------------------------
extern "C" void kernel_launch(void* const* d_in, const int* in_sizes, int n_in,
                              void* d_out, int out_size)
{
    const int*   docs    = (const int*)  d_in[0];
    const float* emb     = (const float*)d_in[1];
    const float* diags   = (const float*)d_in[2];
    const float* bias    = (const float*)d_in[3];
    const float* epsilon = (const float*)d_in[4];
    const float* w1      = (const float*)d_in[5];
    const float* b1      = (const float*)d_in[6];
    const float* w2      = (const float*)d_in[7];
    const float* b2      = (const float*)d_in[8];
    const float* w3      = (const float*)d_in[9];
    const float* b3      = (const float*)d_in[10];
    float* out = (float*)d_out;

    cudaFuncSetAttribute(gemm_hmma_kernel,
                         cudaFuncAttributeMaxDynamicSharedMemorySize, SMEM_DYN);

    dedup_clear_kernel<<<(Vv + 255) / 256, 256>>>();
    dedup_mark_kernel<<<(Mtot + 255) / 256, 256>>>(docs);
    dedup_scan_kernel<<<1, 1024>>>();
    dedup_uid_kernel<<<(Mtot + 255) / 256, 256>>>(docs);

    conv_emb_kernel<<<Mtot, Kp>>>(emb);
    conv_diag_kernel<<<Np, Kp>>>(diags);

    dim3 gridG(Np / TN, Mtot / TM);   // (22, 256); CTAs beyond count exit
    gemm_hmma_kernel<<<gridG, 256, SMEM_DYN>>>(bias);

    dim3 gridS(Bn, NCH);              // (64, 4)
    scan_part_kernel<<<gridS, 256>>>(epsilon);
    scan_combine_kernel<<<(Bn * Pn + 127) / 128, 128>>>();

    mlp_kernel<<<Bn, 128>>>(w1, b1, w2, b2, w3, b3, out);
}

// round 11
// speedup vs baseline: 1.4103x; 1.4103x over previous
#include <cuda_runtime.h>
#include <cuda_bf16.h>
#include <math.h>
#include <stdint.h>

// Problem constants
#define Bn   64
#define Ln   512
#define En   300
#define Vv   50000
#define Pn   200
#define Dn   2800          // P * 2 * M
#define Hn   100
#define Mtot (Bn * Ln)     // 32768
#define NEG  (-100.0f)
#define NINF (-1.0e30f)

// GEMM config: logical K' = 3*320 (hi*hi, hi*lo, lo*hi), stored K2 = 2*320
#define Kp    320
#define K2    640
#define Np    2816
#define TM    128
#define TN    128
#define BK    32                 // bf16 per k-tile
#define NKT   30                 // 3 terms x 10 chunks (chunk 9: ks=0 only)
#define ROWB  80u                // padded smem row stride (bytes) per 32-bf16 row
#define ASZ   (128u * ROWB)      // 10240
#define STAGE (2u * ASZ)         // A + B = 20480
#define NSTG  3
#define SMEM_DYN (NSTG * STAGE)  // 61440

// Scan split config
#define NCH   4
#define CL    (Ln / NCH)         // 128

// Scratch (static device globals — no dynamic allocation)
__device__ float                        g_scores[Bn * Pn];
__device__ __align__(256) float         g_tsu[(size_t)Mtot * Np];  // [uid][n]
__device__ __align__(256) float         g_part[(size_t)Bn * Pn * NCH * 64];
__device__ __align__(256) __nv_bfloat16 g_A2[(size_t)Mtot * K2];
__device__ __align__(256) __nv_bfloat16 g_B2[(size_t)Np * K2];
__device__ int g_flag[Vv];
__device__ int g_tok[Mtot];
__device__ int g_uid[Mtot];
__device__ int g_count;

// ---------------------------------------------------------------------------
// PTX helpers (baseline PTX only — no 'a'-target instructions)
// ---------------------------------------------------------------------------
__device__ __forceinline__ uint32_t s2u(const void* p) {
    uint32_t a;
    asm("{ .reg .u64 t; cvta.to.shared.u64 t, %1; cvt.u32.u64 %0, t; }"
        : "=r"(a) : "l"(p));
    return a;
}

#define CP_ASYNC16(dst, src) \
    asm volatile("cp.async.cg.shared.global [%0], [%1], 16;" :: "r"(dst), "l"(src) : "memory")
#define CP_COMMIT() asm volatile("cp.async.commit_group;" ::: "memory")
#define CP_WAIT(n)  asm volatile("cp.async.wait_group %0;" :: "n"(n) : "memory")

#define LDSM_X4(r, addr)                                                        \
    asm volatile("ldmatrix.sync.aligned.m8n8.x4.shared.b16 {%0,%1,%2,%3}, [%4];" \
        : "=r"((r)[0]), "=r"((r)[1]), "=r"((r)[2]), "=r"((r)[3]) : "r"(addr))

#define LDSM_X4_B(r0, r1, r2, r3, addr)                                         \
    asm volatile("ldmatrix.sync.aligned.m8n8.x4.shared.b16 {%0,%1,%2,%3}, [%4];" \
        : "=r"(r0), "=r"(r1), "=r"(r2), "=r"(r3) : "r"(addr))

#define MMA_BF16(d, a, b)                                                       \
    asm volatile("mma.sync.aligned.m16n8k16.row.col.f32.bf16.bf16.f32 "         \
        "{%0,%1,%2,%3}, {%4,%5,%6,%7}, {%8,%9}, {%0,%1,%2,%3};"                 \
        : "+f"((d)[0]), "+f"((d)[1]), "+f"((d)[2]), "+f"((d)[3])                \
        : "r"((a)[0]), "r"((a)[1]), "r"((a)[2]), "r"((a)[3]),                   \
          "r"((b)[0]), "r"((b)[1]))

// ---------------------------------------------------------------------------
// Dedup: flag -> prefix scan (deterministic) -> uid maps
// ---------------------------------------------------------------------------
__global__ void dedup_clear_kernel() {
    const int i = blockIdx.x * blockDim.x + threadIdx.x;
    if (i < Vv) g_flag[i] = 0;
}
__global__ void dedup_mark_kernel(const int* __restrict__ docs) {
    const int m = blockIdx.x * blockDim.x + threadIdx.x;
    if (m < Mtot) g_flag[docs[m]] = 1;       // racing writes of 1: benign
}
__global__ void __launch_bounds__(1024) dedup_scan_kernel() {
    __shared__ int ss[1024];
    const int tid = threadIdx.x;
    const int CHUNK = (Vv + 1023) / 1024;    // 49
    const int base = tid * CHUNK;
    int s = 0;
    for (int i = 0; i < CHUNK; i++) {
        const int v = base + i;
        if (v < Vv) s += g_flag[v];
    }
    ss[tid] = s;
    __syncthreads();
    for (int off = 1; off < 1024; off <<= 1) {
        int v = (tid >= off) ? ss[tid - off] : 0;
        __syncthreads();
        ss[tid] += v;
        __syncthreads();
    }
    int run = (tid == 0) ? 0 : ss[tid - 1];
    if (tid == 1023) g_count = ss[1023];
    for (int i = 0; i < CHUNK; i++) {
        const int v = base + i;
        if (v < Vv && g_flag[v]) {
            g_tok[run] = v;
            g_flag[v] = run + 1;             // uid+1 (0 = unused)
            run++;
        }
    }
}
__global__ void dedup_uid_kernel(const int* __restrict__ docs) {
    const int m = blockIdx.x * blockDim.x + threadIdx.x;
    if (m < Mtot) g_uid[m] = g_flag[docs[m]] - 1;
}

// ---------------------------------------------------------------------------
// Conversion: fp32 -> bf16 hi/lo; rows are [hi(320) | lo(320)]
// ---------------------------------------------------------------------------
__global__ void conv_emb_kernel(const float* __restrict__ emb)
{
    const int u = blockIdx.x;
    if (u >= g_count) return;
    const int k = threadIdx.x;          // 0..319
    const int tok = g_tok[u];
    float x = (k < En) ? emb[(size_t)tok * En + k] : 0.0f;
    __nv_bfloat16 hi = __float2bfloat16(x);
    __nv_bfloat16 lo = __float2bfloat16(x - __bfloat162float(hi));
    __nv_bfloat16* row = g_A2 + (size_t)u * K2;
    row[k] = hi;  row[Kp + k] = lo;
}

__global__ void conv_diag_kernel(const float* __restrict__ diags)
{
    const int d = blockIdx.x;           // 0..2815
    const int k = threadIdx.x;
    float x = (d < Dn && k < En) ? diags[(size_t)d * En + k] : 0.0f;
    __nv_bfloat16 hi = __float2bfloat16(x);
    __nv_bfloat16 lo = __float2bfloat16(x - __bfloat162float(hi));
    __nv_bfloat16* row = g_B2 + (size_t)d * K2;
    row[k] = hi;  row[Kp + k] = lo;
}

// ---------------------------------------------------------------------------
// Kernel 1: bf16 HMMA GEMM over uid rows.  ts_u[u,n] = A2[u]·B2[n] + bias[n]
// Term t = kt/10: A uses {hi,hi,lo}[t], B uses {hi,lo,hi}[t].
// Chunks kt%10==9 cover k 288..319; cols 304..319 are zero -> ks=1 skipped.
// ---------------------------------------------------------------------------
__global__ void __launch_bounds__(256, 2)
gemm_hmma_kernel(const float* __restrict__ bias)
{
    const int m0 = blockIdx.y * TM;
    const int cnt = g_count;
    if (m0 >= cnt) return;              // uniform per-CTA exit

    extern __shared__ char smem[];
    const uint32_t sbase = s2u(smem);

    const int tid  = threadIdx.x;
    const int wid  = tid >> 5;
    const int lane = tid & 31;
    const int wm   = wid & 3;            // 0..3  (M)
    const int wn   = wid >> 2;           // 0..1  (N)
    const int n0   = blockIdx.x * TN;

    const uint32_t aoff = (uint32_t)((((lane >> 3) & 1) * 8 + (lane & 7)) * ROWB
                                     + ((lane >> 4) * 8) * 2);
    const uint32_t boff = (uint32_t)(((lane >> 4) * 8 + (lane & 7)) * ROWB
                                     + (((lane >> 3) & 1) * 8) * 2);

    const int cr0 = tid >> 2;            // rows 0..63 (+64)
    const int cc  = (tid & 3) * 8;       // bf16 col offset

    auto load_stage = [&](int buf, int kt) {
        const uint32_t sb = sbase + (uint32_t)buf * STAGE;
        const int t  = kt / 10;
        const int ck = kt - t * 10;
        const int kk = ck * BK;
        const int ak = (t == 2 ? Kp : 0) + kk;   // A: hi, hi, lo
        const int bk = (t == 1 ? Kp : 0) + kk;   // B: hi, lo, hi
        const bool used = (ck != 9) || (cc < 16);   // cols 304+ never consumed
        if (used) {
            #pragma unroll
            for (int u = 0; u < 2; u++) {
                const int r = cr0 + u * 64;
                CP_ASYNC16(sb + (uint32_t)r * ROWB + (uint32_t)(cc * 2),
                           g_A2 + (size_t)(m0 + r) * K2 + ak + cc);
            }
            #pragma unroll
            for (int u = 0; u < 2; u++) {
                const int r = cr0 + u * 64;
                CP_ASYNC16(sb + ASZ + (uint32_t)r * ROWB + (uint32_t)(cc * 2),
                           g_B2 + (size_t)(n0 + r) * K2 + bk + cc);
            }
        }
        CP_COMMIT();
    };

    float c[2][8][4];
    #pragma unroll
    for (int i = 0; i < 2; i++)
        #pragma unroll
        for (int j = 0; j < 8; j++)
            #pragma unroll
            for (int q = 0; q < 4; q++) c[i][j][q] = 0.f;

    load_stage(0, 0);
    load_stage(1, 1);

    for (int kt = 0; kt < NKT; kt++) {
        if (kt < NKT - 1) CP_WAIT(1);
        else              CP_WAIT(0);
        __syncthreads();

        if (kt + 2 < NKT) load_stage((kt + 2) % NSTG, kt + 2);

        const uint32_t sA = sbase + (uint32_t)(kt % NSTG) * STAGE;
        const uint32_t sB = sA + ASZ;

        auto do_ks = [&](int ks) {
            uint32_t a[2][4], bfr[8][2];
            #pragma unroll
            for (int i = 0; i < 2; i++)
                LDSM_X4(a[i], sA + (uint32_t)((wm * 32 + i * 16) * ROWB) + (uint32_t)(ks * 32) + aoff);
            #pragma unroll
            for (int j2 = 0; j2 < 4; j2++)
                LDSM_X4_B(bfr[j2 * 2][0], bfr[j2 * 2][1],
                          bfr[j2 * 2 + 1][0], bfr[j2 * 2 + 1][1],
                          sB + (uint32_t)((wn * 64 + j2 * 16) * ROWB) + (uint32_t)(ks * 32) + boff);
            #pragma unroll
            for (int i = 0; i < 2; i++)
                #pragma unroll
                for (int j = 0; j < 8; j++)
                    MMA_BF16(c[i][j], a[i], bfr[j]);
        };

        do_ks(0);
        if (kt % 10 != 9) do_ks(1);       // tail chunk: k 304..319 are all zero
    }

    // ---- epilogue: plain [uid][n] store with bias ----
    const int gid = lane >> 2;
    const int tig = lane & 3;
    #pragma unroll
    for (int i = 0; i < 2; i++) {
        const int r0 = m0 + wm * 32 + i * 16 + gid;
        #pragma unroll
        for (int j = 0; j < 8; j++) {
            const int n = n0 + wn * 64 + j * 8 + tig * 2;
            const float bx = __ldg(bias + (n < Dn ? n : 0));
            const float by = __ldg(bias + (n + 1 < Dn ? n + 1 : 0));
            #pragma unroll
            for (int h = 0; h < 2; h++) {
                const int m = r0 + h * 8;
                if (m < cnt) {
                    *reinterpret_cast<float2*>(g_tsu + (size_t)m * Np + n) =
                        make_float2(c[i][j][h * 2] + bx, c[i][j][h * 2 + 1] + by);
                }
            }
        }
    }
}

// ---------------------------------------------------------------------------
// Kernel 2a: chunked max-plus scan; each ts row read ONCE per (b,ch) block
// (all 200 patterns resident in one 256-thread block). Triangular basis.
// Slot layout (64 floats): [0..48] M cols j*7+i, [49..55] C, [56..63] S.
// ---------------------------------------------------------------------------
__global__ void __launch_bounds__(256)
scan_part_kernel(const float* __restrict__ epsilon)
{
    const int b   = blockIdx.x;
    const int ch  = blockIdx.y;
    const int tid = threadIdx.x;

    __shared__ int uids[CL];
    for (int i = tid; i < CL; i += 256)
        uids[i] = g_uid[b * Ln + ch * CL + i];
    __syncthreads();
    if (tid >= Pn) return;
    const int p = tid;

    float e[6];
    #pragma unroll
    for (int j = 0; j < 6; j++) e[j] = __ldg(epsilon + p * 6 + j);

    float h[8][7];
    #pragma unroll
    for (int j = 0; j < 8; j++)
        #pragma unroll
        for (int i = 0; i < 7; i++) h[j][i] = NINF;
    #pragma unroll
    for (int j = 0; j < 7; j++) h[j][j] = 0.0f;
    float smax[8];
    #pragma unroll
    for (int j = 0; j < 8; j++) smax[j] = NINF;

    const int poff = p * 14;

    float2 nxv[7];
    {
        const float* r = g_tsu + (size_t)uids[0] * Np + poff;
        #pragma unroll
        for (int q = 0; q < 7; q++) nxv[q] = *reinterpret_cast<const float2*>(r + 2 * q);
    }

    for (int l = 0; l < CL; l++) {
        float xv[14];
        #pragma unroll
        for (int q = 0; q < 7; q++) { xv[2 * q] = nxv[q].x; xv[2 * q + 1] = nxv[q].y; }
        if (l + 1 < CL) {
            const float* r = g_tsu + (size_t)uids[l + 1] * Np + poff;
            #pragma unroll
            for (int q = 0; q < 7; q++) nxv[q] = *reinterpret_cast<const float2*>(r + 2 * q);
        }

        // basis columns j = 0..6 (triangular: states < j stay NINF)
        #pragma unroll
        for (int j = 0; j < 7; j++) {
            float nh[7];
            float aeprev = h[j][j];                 // ae[j]
            nh[j] = aeprev + xv[j];                 // pure self-loop at state j
            #pragma unroll
            for (int m = j + 1; m < 7; m++) {
                const float aem = fmaxf(h[j][m], h[j][m - 1] + e[m - 1]);
                nh[m] = fmaxf(aeprev + xv[7 + m - 1], aem + xv[m]);
                aeprev = aem;
            }
            smax[j] = fmaxf(smax[j], nh[6]);
            #pragma unroll
            for (int m = j; m < 7; m++) h[j][m] = nh[m];
        }
        // const column (exact reference semantics incl. restart)
        {
            float ae[7];
            ae[0] = fmaxf(h[7][0], NEG);
            #pragma unroll
            for (int m = 1; m < 7; m++) ae[m] = fmaxf(h[7][m], h[7][m - 1] + e[m - 1]);
            float nh[7];
            nh[0] = fmaxf(0.0f, ae[0] + xv[0]);
            #pragma unroll
            for (int m = 1; m < 7; m++)
                nh[m] = fmaxf(ae[m - 1] + xv[7 + m - 1], ae[m] + xv[m]);
            smax[7] = fmaxf(smax[7], nh[6]);
            #pragma unroll
            for (int m = 0; m < 7; m++) h[7][m] = nh[m];
        }
    }

    float* slot = g_part + ((size_t)(b * Pn + p) * NCH + ch) * 64;
    #pragma unroll
    for (int j = 0; j < 7; j++)
        #pragma unroll
        for (int i = 0; i < 7; i++) slot[j * 7 + i] = (i >= j) ? h[j][i] : NINF;
    #pragma unroll
    for (int i = 0; i < 7; i++) slot[49 + i] = h[7][i];
    #pragma unroll
    for (int j = 0; j < 8; j++) slot[56 + j] = smax[j];
}

// ---------------------------------------------------------------------------
// Kernel 2b: combine the NCH chunk transforms per chain.
// ---------------------------------------------------------------------------
__global__ void scan_combine_kernel()
{
    const int bp = blockIdx.x * blockDim.x + threadIdx.x;
    if (bp >= Bn * Pn) return;

    float h[7];
    h[0] = 0.0f;
    #pragma unroll
    for (int i = 1; i < 7; i++) h[i] = NEG;
    float s = NEG;

    #pragma unroll 1
    for (int c = 0; c < NCH; c++) {
        const float* sl = g_part + ((size_t)bp * NCH + c) * 64;
        float ns = fmaxf(s, sl[63]);
        #pragma unroll
        for (int j = 0; j < 7; j++) ns = fmaxf(ns, sl[56 + j] + h[j]);
        float nh[7];
        #pragma unroll
        for (int i = 0; i < 7; i++) {
            float v = sl[49 + i];
            #pragma unroll
            for (int j = 0; j < 7; j++) v = fmaxf(v, sl[j * 7 + i] + h[j]);
            nh[i] = v;
        }
        #pragma unroll
        for (int i = 0; i < 7; i++) h[i] = nh[i];
        s = ns;
    }
    g_scores[bp] = s;
}

// ---------------------------------------------------------------------------
// Kernel 3: MLP + log_softmax. One block per batch row.
// ---------------------------------------------------------------------------
__global__ void mlp_kernel(const float* __restrict__ w1, const float* __restrict__ b1,
                           const float* __restrict__ w2, const float* __restrict__ b2,
                           const float* __restrict__ w3, const float* __restrict__ b3,
                           float* __restrict__ out)
{
    const int b = blockIdx.x;
    const int tid = threadIdx.x;
    __shared__ float sc[Pn];
    __shared__ float h1[Hn];
    __shared__ float h2[Hn];

    for (int i = tid; i < Pn; i += blockDim.x) sc[i] = g_scores[b * Pn + i];
    __syncthreads();

    if (tid < Hn) {
        float acc = b1[tid];
        #pragma unroll 4
        for (int p = 0; p < Pn; p++) acc = fmaf(sc[p], w1[p * Hn + tid], acc);
        h1[tid] = fmaxf(acc, 0.f);
    }
    __syncthreads();

    if (tid < Hn) {
        float acc = b2[tid];
        #pragma unroll 4
        for (int j = 0; j < Hn; j++) acc = fmaf(h1[j], w2[j * Hn + tid], acc);
        h2[tid] = fmaxf(acc, 0.f);
    }
    __syncthreads();

    if (tid == 0) {
        float l0 = b3[0], l1 = b3[1];
        for (int j = 0; j < Hn; j++) {
            l0 = fmaf(h2[j], w3[j * 2 + 0], l0);
            l1 = fmaf(h2[j], w3[j * 2 + 1], l1);
        }
        float mx  = fmaxf(l0, l1);
        float lse = mx + logf(expf(l0 - mx) + expf(l1 - mx));
        out[b * 2 + 0] = l0 - lse;
        out[b * 2 + 1] = l1 - lse;
    }
}

// ---------------------------------------------------------------------------
extern "C" void kernel_launch(void* const* d_in, const int* in_sizes, int n_in,
                              void* d_out, int out_size)
{
    const int*   docs    = (const int*)  d_in[0];
    const float* emb     = (const float*)d_in[1];
    const float* diags   = (const float*)d_in[2];
    const float* bias    = (const float*)d_in[3];
    const float* epsilon = (const float*)d_in[4];
    const float* w1      = (const float*)d_in[5];
    const float* b1      = (const float*)d_in[6];
    const float* w2      = (const float*)d_in[7];
    const float* b2      = (const float*)d_in[8];
    const float* w3      = (const float*)d_in[9];
    const float* b3      = (const float*)d_in[10];
    float* out = (float*)d_out;

    cudaFuncSetAttribute(gemm_hmma_kernel,
                         cudaFuncAttributeMaxDynamicSharedMemorySize, SMEM_DYN);

    dedup_clear_kernel<<<(Vv + 255) / 256, 256>>>();
    dedup_mark_kernel<<<(Mtot + 255) / 256, 256>>>(docs);
    dedup_scan_kernel<<<1, 1024>>>();
    dedup_uid_kernel<<<(Mtot + 255) / 256, 256>>>(docs);

    conv_emb_kernel<<<Mtot, Kp>>>(emb);
    conv_diag_kernel<<<Np, Kp>>>(diags);

    dim3 gridG(Np / TN, Mtot / TM);   // (22, 256); CTAs beyond count exit
    gemm_hmma_kernel<<<gridG, 256, SMEM_DYN>>>(bias);

    dim3 gridS(Bn, NCH);              // (64, 4)
    scan_part_kernel<<<gridS, 256>>>(epsilon);
    scan_combine_kernel<<<(Bn * Pn + 127) / 128, 128>>>();

    mlp_kernel<<<Bn, 128>>>(w1, b1, w2, b2, w3, b3, out);
}

// round 12
// speedup vs baseline: 1.7692x; 1.2545x over previous
#include <cuda_runtime.h>
#include <cuda_bf16.h>
#include <cuda_fp16.h>
#include <math.h>
#include <stdint.h>

// Problem constants
#define Bn   64
#define Ln   512
#define En   300
#define Vv   50000
#define Pn   200
#define Dn   2800          // P * 2 * M
#define Hn   100
#define Mtot (Bn * Ln)     // 32768
#define NEG  (-100.0f)
#define NINF (-1.0e30f)

// GEMM config: fp16 2-term split. A = ah (K=320). B = [bh | bl] (K2=640).
// ts = ah·bh + ah·bl = ah·b  (dropped term (a-ah)·b ~ 2.8e-4 abs)
#define Kp    320
#define K2    640
#define Np    2816
#define TM    128
#define TN    128
#define BK    32                 // fp16 per k-tile
#define NKT   20                 // 2 terms x 10 chunks (chunk 9: ks=0 only)
#define ROWB  80u                // padded smem row stride (bytes) per 32-fp16 row
#define ASZ   (128u * ROWB)      // 10240
#define STAGE (2u * ASZ)         // A + B = 20480
#define NSTG  3
#define SMEM_DYN (NSTG * STAGE)  // 61440

// Scan split config
#define NCH   4
#define CL    (Ln / NCH)         // 128

// Scratch (static device globals — no dynamic allocation)
__device__ float                 g_scores[Bn * Pn];
__device__ __align__(256) float  g_tsu[(size_t)Mtot * Np];  // [uid][n]
__device__ __align__(256) float  g_part[(size_t)Bn * Pn * NCH * 64];
__device__ __align__(256) __half g_A2[(size_t)Mtot * Kp];   // ah
__device__ __align__(256) __half g_B2[(size_t)Np * K2];     // [bh | bl]
__device__ int g_flag[Vv];
__device__ int g_tok[Mtot];
__device__ int g_uid[Mtot];
__device__ int g_count;

// ---------------------------------------------------------------------------
// PTX helpers (baseline PTX only — no 'a'-target instructions)
// ---------------------------------------------------------------------------
__device__ __forceinline__ uint32_t s2u(const void* p) {
    uint32_t a;
    asm("{ .reg .u64 t; cvta.to.shared.u64 t, %1; cvt.u32.u64 %0, t; }"
        : "=r"(a) : "l"(p));
    return a;
}

#define CP_ASYNC16(dst, src) \
    asm volatile("cp.async.cg.shared.global [%0], [%1], 16;" :: "r"(dst), "l"(src) : "memory")
#define CP_COMMIT() asm volatile("cp.async.commit_group;" ::: "memory")
#define CP_WAIT(n)  asm volatile("cp.async.wait_group %0;" :: "n"(n) : "memory")

#define LDSM_X4(r, addr)                                                        \
    asm volatile("ldmatrix.sync.aligned.m8n8.x4.shared.b16 {%0,%1,%2,%3}, [%4];" \
        : "=r"((r)[0]), "=r"((r)[1]), "=r"((r)[2]), "=r"((r)[3]) : "r"(addr))

#define LDSM_X4_B(r0, r1, r2, r3, addr)                                         \
    asm volatile("ldmatrix.sync.aligned.m8n8.x4.shared.b16 {%0,%1,%2,%3}, [%4];" \
        : "=r"(r0), "=r"(r1), "=r"(r2), "=r"(r3) : "r"(addr))

#define MMA_F16(d, a, b)                                                        \
    asm volatile("mma.sync.aligned.m16n8k16.row.col.f32.f16.f16.f32 "           \
        "{%0,%1,%2,%3}, {%4,%5,%6,%7}, {%8,%9}, {%0,%1,%2,%3};"                 \
        : "+f"((d)[0]), "+f"((d)[1]), "+f"((d)[2]), "+f"((d)[3])                \
        : "r"((a)[0]), "r"((a)[1]), "r"((a)[2]), "r"((a)[3]),                   \
          "r"((b)[0]), "r"((b)[1]))

// ---------------------------------------------------------------------------
// Dedup: flag -> prefix scan (deterministic) -> uid maps
// ---------------------------------------------------------------------------
__global__ void dedup_clear_kernel() {
    const int i = blockIdx.x * blockDim.x + threadIdx.x;
    if (i < Vv) g_flag[i] = 0;
}
__global__ void dedup_mark_kernel(const int* __restrict__ docs) {
    const int m = blockIdx.x * blockDim.x + threadIdx.x;
    if (m < Mtot) g_flag[docs[m]] = 1;       // racing writes of 1: benign
}
__global__ void __launch_bounds__(1024) dedup_scan_kernel() {
    __shared__ int ss[1024];
    const int tid = threadIdx.x;
    const int CHUNK = (Vv + 1023) / 1024;    // 49
    const int base = tid * CHUNK;
    int s = 0;
    for (int i = 0; i < CHUNK; i++) {
        const int v = base + i;
        if (v < Vv) s += g_flag[v];
    }
    ss[tid] = s;
    __syncthreads();
    for (int off = 1; off < 1024; off <<= 1) {
        int v = (tid >= off) ? ss[tid - off] : 0;
        __syncthreads();
        ss[tid] += v;
        __syncthreads();
    }
    int run = (tid == 0) ? 0 : ss[tid - 1];
    if (tid == 1023) g_count = ss[1023];
    for (int i = 0; i < CHUNK; i++) {
        const int v = base + i;
        if (v < Vv && g_flag[v]) {
            g_tok[run] = v;
            g_flag[v] = run + 1;             // uid+1 (0 = unused)
            run++;
        }
    }
}
__global__ void dedup_uid_kernel(const int* __restrict__ docs) {
    const int m = blockIdx.x * blockDim.x + threadIdx.x;
    if (m < Mtot) g_uid[m] = g_flag[docs[m]] - 1;
}

// ---------------------------------------------------------------------------
// Conversion: A -> fp16 ah; B -> fp16 [bh | bl]
// ---------------------------------------------------------------------------
__global__ void conv_emb_kernel(const float* __restrict__ emb)
{
    const int u = blockIdx.x;
    if (u >= g_count) return;
    const int k = threadIdx.x;          // 0..319
    const int tok = g_tok[u];
    float x = (k < En) ? emb[(size_t)tok * En + k] : 0.0f;
    g_A2[(size_t)u * Kp + k] = __float2half_rn(x);
}

__global__ void conv_diag_kernel(const float* __restrict__ diags)
{
    const int d = blockIdx.x;           // 0..2815
    const int k = threadIdx.x;
    float x = (d < Dn && k < En) ? diags[(size_t)d * En + k] : 0.0f;
    __half hi = __float2half_rn(x);
    __half lo = __float2half_rn(x - __half2float(hi));
    __half* row = g_B2 + (size_t)d * K2;
    row[k] = hi;  row[Kp + k] = lo;
}

// ---------------------------------------------------------------------------
// Kernel 1: fp16 HMMA GEMM over uid rows.  ts_u[u,n] = ah[u]·(bh+bl)[n] + bias[n]
// Term t = kt/10: A uses ah always, B uses {bh, bl}[t].
// Chunks kt%10==9 cover k 288..319; cols 304..319 are zero -> ks=1 skipped.
// ---------------------------------------------------------------------------
__global__ void __launch_bounds__(256, 2)
gemm_hmma_kernel(const float* __restrict__ bias)
{
    const int m0 = blockIdx.y * TM;
    const int cnt = g_count;
    if (m0 >= cnt) return;              // uniform per-CTA exit

    extern __shared__ char smem[];
    const uint32_t sbase = s2u(smem);

    const int tid  = threadIdx.x;
    const int wid  = tid >> 5;
    const int lane = tid & 31;
    const int wm   = wid & 3;            // 0..3  (M)
    const int wn   = wid >> 2;           // 0..1  (N)
    const int n0   = blockIdx.x * TN;

    const uint32_t aoff = (uint32_t)((((lane >> 3) & 1) * 8 + (lane & 7)) * ROWB
                                     + ((lane >> 4) * 8) * 2);
    const uint32_t boff = (uint32_t)(((lane >> 4) * 8 + (lane & 7)) * ROWB
                                     + (((lane >> 3) & 1) * 8) * 2);

    const int cr0 = tid >> 2;            // rows 0..63 (+64)
    const int cc  = (tid & 3) * 8;       // fp16 col offset

    auto load_stage = [&](int buf, int kt) {
        const uint32_t sb = sbase + (uint32_t)buf * STAGE;
        const int t  = kt / 10;
        const int ck = kt - t * 10;
        const int kk = ck * BK;
        const int bk = t * Kp + kk;              // B: bh, bl
        const bool used = (ck != 9) || (cc < 16);   // cols 304+ never consumed
        if (used) {
            #pragma unroll
            for (int u = 0; u < 2; u++) {
                const int r = cr0 + u * 64;
                CP_ASYNC16(sb + (uint32_t)r * ROWB + (uint32_t)(cc * 2),
                           g_A2 + (size_t)(m0 + r) * Kp + kk + cc);
            }
            #pragma unroll
            for (int u = 0; u < 2; u++) {
                const int r = cr0 + u * 64;
                CP_ASYNC16(sb + ASZ + (uint32_t)r * ROWB + (uint32_t)(cc * 2),
                           g_B2 + (size_t)(n0 + r) * K2 + bk + cc);
            }
        }
        CP_COMMIT();
    };

    float c[2][8][4];
    #pragma unroll
    for (int i = 0; i < 2; i++)
        #pragma unroll
        for (int j = 0; j < 8; j++)
            #pragma unroll
            for (int q = 0; q < 4; q++) c[i][j][q] = 0.f;

    load_stage(0, 0);
    load_stage(1, 1);

    for (int kt = 0; kt < NKT; kt++) {
        if (kt < NKT - 1) CP_WAIT(1);
        else              CP_WAIT(0);
        __syncthreads();

        if (kt + 2 < NKT) load_stage((kt + 2) % NSTG, kt + 2);

        const uint32_t sA = sbase + (uint32_t)(kt % NSTG) * STAGE;
        const uint32_t sB = sA + ASZ;

        auto do_ks = [&](int ks) {
            uint32_t a[2][4], bfr[8][2];
            #pragma unroll
            for (int i = 0; i < 2; i++)
                LDSM_X4(a[i], sA + (uint32_t)((wm * 32 + i * 16) * ROWB) + (uint32_t)(ks * 32) + aoff);
            #pragma unroll
            for (int j2 = 0; j2 < 4; j2++)
                LDSM_X4_B(bfr[j2 * 2][0], bfr[j2 * 2][1],
                          bfr[j2 * 2 + 1][0], bfr[j2 * 2 + 1][1],
                          sB + (uint32_t)((wn * 64 + j2 * 16) * ROWB) + (uint32_t)(ks * 32) + boff);
            #pragma unroll
            for (int i = 0; i < 2; i++)
                #pragma unroll
                for (int j = 0; j < 8; j++)
                    MMA_F16(c[i][j], a[i], bfr[j]);
        };

        do_ks(0);
        if (kt % 10 != 9) do_ks(1);       // tail chunk: k 304..319 are all zero
    }

    // ---- epilogue: plain [uid][n] store with bias ----
    const int gid = lane >> 2;
    const int tig = lane & 3;
    #pragma unroll
    for (int i = 0; i < 2; i++) {
        const int r0 = m0 + wm * 32 + i * 16 + gid;
        #pragma unroll
        for (int j = 0; j < 8; j++) {
            const int n = n0 + wn * 64 + j * 8 + tig * 2;
            const float bx = __ldg(bias + (n < Dn ? n : 0));
            const float by = __ldg(bias + (n + 1 < Dn ? n + 1 : 0));
            #pragma unroll
            for (int h = 0; h < 2; h++) {
                const int m = r0 + h * 8;
                if (m < cnt) {
                    *reinterpret_cast<float2*>(g_tsu + (size_t)m * Np + n) =
                        make_float2(c[i][j][h * 2] + bx, c[i][j][h * 2 + 1] + by);
                }
            }
        }
    }
}

// ---------------------------------------------------------------------------
// Kernel 2a: chunked max-plus scan; each ts row read ONCE per (b,ch) block
// (all 200 patterns resident in one 256-thread block). Triangular basis.
// Slot layout (64 floats): [0..48] M cols j*7+i, [49..55] C, [56..63] S.
// ---------------------------------------------------------------------------
__global__ void __launch_bounds__(256)
scan_part_kernel(const float* __restrict__ epsilon)
{
    const int b   = blockIdx.x;
    const int ch  = blockIdx.y;
    const int tid = threadIdx.x;

    __shared__ int uids[CL];
    for (int i = tid; i < CL; i += 256)
        uids[i] = g_uid[b * Ln + ch * CL + i];
    __syncthreads();
    if (tid >= Pn) return;
    const int p = tid;

    float e[6];
    #pragma unroll
    for (int j = 0; j < 6; j++) e[j] = __ldg(epsilon + p * 6 + j);

    float h[8][7];
    #pragma unroll
    for (int j = 0; j < 8; j++)
        #pragma unroll
        for (int i = 0; i < 7; i++) h[j][i] = NINF;
    #pragma unroll
    for (int j = 0; j < 7; j++) h[j][j] = 0.0f;
    float smax[8];
    #pragma unroll
    for (int j = 0; j < 8; j++) smax[j] = NINF;

    const int poff = p * 14;

    float2 nxv[7];
    {
        const float* r = g_tsu + (size_t)uids[0] * Np + poff;
        #pragma unroll
        for (int q = 0; q < 7; q++) nxv[q] = *reinterpret_cast<const float2*>(r + 2 * q);
    }

    for (int l = 0; l < CL; l++) {
        float xv[14];
        #pragma unroll
        for (int q = 0; q < 7; q++) { xv[2 * q] = nxv[q].x; xv[2 * q + 1] = nxv[q].y; }
        if (l + 1 < CL) {
            const float* r = g_tsu + (size_t)uids[l + 1] * Np + poff;
            #pragma unroll
            for (int q = 0; q < 7; q++) nxv[q] = *reinterpret_cast<const float2*>(r + 2 * q);
        }

        // basis columns j = 0..6 (triangular: states < j stay NINF)
        #pragma unroll
        for (int j = 0; j < 7; j++) {
            float nh[7];
            float aeprev = h[j][j];                 // ae[j]
            nh[j] = aeprev + xv[j];                 // pure self-loop at state j
            #pragma unroll
            for (int m = j + 1; m < 7; m++) {
                const float aem = fmaxf(h[j][m], h[j][m - 1] + e[m - 1]);
                nh[m] = fmaxf(aeprev + xv[7 + m - 1], aem + xv[m]);
                aeprev = aem;
            }
            smax[j] = fmaxf(smax[j], nh[6]);
            #pragma unroll
            for (int m = j; m < 7; m++) h[j][m] = nh[m];
        }
        // const column (exact reference semantics incl. restart)
        {
            float ae[7];
            ae[0] = fmaxf(h[7][0], NEG);
            #pragma unroll
            for (int m = 1; m < 7; m++) ae[m] = fmaxf(h[7][m], h[7][m - 1] + e[m - 1]);
            float nh[7];
            nh[0] = fmaxf(0.0f, ae[0] + xv[0]);
            #pragma unroll
            for (int m = 1; m < 7; m++)
                nh[m] = fmaxf(ae[m - 1] + xv[7 + m - 1], ae[m] + xv[m]);
            smax[7] = fmaxf(smax[7], nh[6]);
            #pragma unroll
            for (int m = 0; m < 7; m++) h[7][m] = nh[m];
        }
    }

    float* slot = g_part + ((size_t)(b * Pn + p) * NCH + ch) * 64;
    #pragma unroll
    for (int j = 0; j < 7; j++)
        #pragma unroll
        for (int i = 0; i < 7; i++) slot[j * 7 + i] = (i >= j) ? h[j][i] : NINF;
    #pragma unroll
    for (int i = 0; i < 7; i++) slot[49 + i] = h[7][i];
    #pragma unroll
    for (int j = 0; j < 8; j++) slot[56 + j] = smax[j];
}

// ---------------------------------------------------------------------------
// Kernel 2b: combine the NCH chunk transforms per chain.
// ---------------------------------------------------------------------------
__global__ void scan_combine_kernel()
{
    const int bp = blockIdx.x * blockDim.x + threadIdx.x;
    if (bp >= Bn * Pn) return;

    float h[7];
    h[0] = 0.0f;
    #pragma unroll
    for (int i = 1; i < 7; i++) h[i] = NEG;
    float s = NEG;

    #pragma unroll 1
    for (int c = 0; c < NCH; c++) {
        const float* sl = g_part + ((size_t)bp * NCH + c) * 64;
        float ns = fmaxf(s, sl[63]);
        #pragma unroll
        for (int j = 0; j < 7; j++) ns = fmaxf(ns, sl[56 + j] + h[j]);
        float nh[7];
        #pragma unroll
        for (int i = 0; i < 7; i++) {
            float v = sl[49 + i];
            #pragma unroll
            for (int j = 0; j < 7; j++) v = fmaxf(v, sl[j * 7 + i] + h[j]);
            nh[i] = v;
        }
        #pragma unroll
        for (int i = 0; i < 7; i++) h[i] = nh[i];
        s = ns;
    }
    g_scores[bp] = s;
}

// ---------------------------------------------------------------------------
// Kernel 3: MLP + log_softmax. One block per batch row.
// ---------------------------------------------------------------------------
__global__ void mlp_kernel(const float* __restrict__ w1, const float* __restrict__ b1,
                           const float* __restrict__ w2, const float* __restrict__ b2,
                           const float* __restrict__ w3, const float* __restrict__ b3,
                           float* __restrict__ out)
{
    const int b = blockIdx.x;
    const int tid = threadIdx.x;
    __shared__ float sc[Pn];
    __shared__ float h1[Hn];
    __shared__ float h2[Hn];

    for (int i = tid; i < Pn; i += blockDim.x) sc[i] = g_scores[b * Pn + i];
    __syncthreads();

    if (tid < Hn) {
        float acc = b1[tid];
        #pragma unroll 4
        for (int p = 0; p < Pn; p++) acc = fmaf(sc[p], w1[p * Hn + tid], acc);
        h1[tid] = fmaxf(acc, 0.f);
    }
    __syncthreads();

    if (tid < Hn) {
        float acc = b2[tid];
        #pragma unroll 4
        for (int j = 0; j < Hn; j++) acc = fmaf(h1[j], w2[j * Hn + tid], acc);
        h2[tid] = fmaxf(acc, 0.f);
    }
    __syncthreads();

    if (tid == 0) {
        float l0 = b3[0], l1 = b3[1];
        for (int j = 0; j < Hn; j++) {
            l0 = fmaf(h2[j], w3[j * 2 + 0], l0);
            l1 = fmaf(h2[j], w3[j * 2 + 1], l1);
        }
        float mx  = fmaxf(l0, l1);
        float lse = mx + logf(expf(l0 - mx) + expf(l1 - mx));
        out[b * 2 + 0] = l0 - lse;
        out[b * 2 + 1] = l1 - lse;
    }
}

// ---------------------------------------------------------------------------
extern "C" void kernel_launch(void* const* d_in, const int* in_sizes, int n_in,
                              void* d_out, int out_size)
{
    const int*   docs    = (const int*)  d_in[0];
    const float* emb     = (const float*)d_in[1];
    const float* diags   = (const float*)d_in[2];
    const float* bias    = (const float*)d_in[3];
    const float* epsilon = (const float*)d_in[4];
    const float* w1      = (const float*)d_in[5];
    const float* b1      = (const float*)d_in[6];
    const float* w2      = (const float*)d_in[7];
    const float* b2      = (const float*)d_in[8];
    const float* w3      = (const float*)d_in[9];
    const float* b3      = (const float*)d_in[10];
    float* out = (float*)d_out;

    cudaFuncSetAttribute(gemm_hmma_kernel,
                         cudaFuncAttributeMaxDynamicSharedMemorySize, SMEM_DYN);

    dedup_clear_kernel<<<(Vv + 255) / 256, 256>>>();
    dedup_mark_kernel<<<(Mtot + 255) / 256, 256>>>(docs);
    dedup_scan_kernel<<<1, 1024>>>();
    dedup_uid_kernel<<<(Mtot + 255) / 256, 256>>>(docs);

    conv_emb_kernel<<<Mtot, Kp>>>(emb);
    conv_diag_kernel<<<Np, Kp>>>(diags);

    dim3 gridG(Np / TN, Mtot / TM);   // (22, 256); CTAs beyond count exit
    gemm_hmma_kernel<<<gridG, 256, SMEM_DYN>>>(bias);

    dim3 gridS(Bn, NCH);              // (64, 4)
    scan_part_kernel<<<gridS, 256>>>(epsilon);
    scan_combine_kernel<<<(Bn * Pn + 127) / 128, 128>>>();

    mlp_kernel<<<Bn, 128>>>(w1, b1, w2, b2, w3, b3, out);
}

// round 13
// speedup vs baseline: 2.3598x; 1.3338x over previous
#include <cuda_runtime.h>
#include <cuda_bf16.h>
#include <cuda_fp16.h>
#include <math.h>
#include <stdint.h>

// Problem constants
#define Bn   64
#define Ln   512
#define En   300
#define Vv   50000
#define Pn   200
#define Dn   2800          // P * 2 * M
#define Hn   100
#define Mtot (Bn * Ln)     // 32768
#define NEG  (-100.0f)
#define NINF (-1.0e30f)

// GEMM config: plain fp16 GEMM, K padded 300->320.
// ts = fp16(a)·fp16(b); both rounding cross-terms dropped (~2e-4 rel out).
#define Kp    320
#define Np    2816
#define TM    128
#define TN    128
#define BK    32                 // fp16 per k-tile
#define NKT   10                 // 10 chunks (chunk 9: ks=0 only; k 304+ zero)
#define ROWB  80u                // padded smem row stride (bytes) per 32-fp16 row
#define ASZ   (128u * ROWB)      // 10240
#define STAGE (2u * ASZ)         // A + B = 20480
#define NSTG  3
#define SMEM_DYN (NSTG * STAGE)  // 61440

// Scan split config
#define NCH   4
#define CL    (Ln / NCH)         // 128

// Scratch (static device globals — no dynamic allocation)
__device__ float                 g_scores[Bn * Pn];
__device__ __align__(256) float  g_tsu[(size_t)Mtot * Np];  // [uid][n]
__device__ __align__(256) float  g_part[(size_t)Bn * Pn * NCH * 64];
__device__ __align__(256) __half g_A2[(size_t)Mtot * Kp];   // fp16(a)
__device__ __align__(256) __half g_B2[(size_t)Np * Kp];     // fp16(b)
__device__ int g_flag[Vv];
__device__ int g_tok[Mtot];
__device__ int g_uid[Mtot];
__device__ int g_count;

// ---------------------------------------------------------------------------
// PTX helpers (baseline PTX only — no 'a'-target instructions)
// ---------------------------------------------------------------------------
__device__ __forceinline__ uint32_t s2u(const void* p) {
    uint32_t a;
    asm("{ .reg .u64 t; cvta.to.shared.u64 t, %1; cvt.u32.u64 %0, t; }"
        : "=r"(a) : "l"(p));
    return a;
}

#define CP_ASYNC16(dst, src) \
    asm volatile("cp.async.cg.shared.global [%0], [%1], 16;" :: "r"(dst), "l"(src) : "memory")
#define CP_COMMIT() asm volatile("cp.async.commit_group;" ::: "memory")
#define CP_WAIT(n)  asm volatile("cp.async.wait_group %0;" :: "n"(n) : "memory")

#define LDSM_X4(r, addr)                                                        \
    asm volatile("ldmatrix.sync.aligned.m8n8.x4.shared.b16 {%0,%1,%2,%3}, [%4];" \
        : "=r"((r)[0]), "=r"((r)[1]), "=r"((r)[2]), "=r"((r)[3]) : "r"(addr))

#define LDSM_X4_B(r0, r1, r2, r3, addr)                                         \
    asm volatile("ldmatrix.sync.aligned.m8n8.x4.shared.b16 {%0,%1,%2,%3}, [%4];" \
        : "=r"(r0), "=r"(r1), "=r"(r2), "=r"(r3) : "r"(addr))

#define MMA_F16(d, a, b)                                                        \
    asm volatile("mma.sync.aligned.m16n8k16.row.col.f32.f16.f16.f32 "           \
        "{%0,%1,%2,%3}, {%4,%5,%6,%7}, {%8,%9}, {%0,%1,%2,%3};"                 \
        : "+f"((d)[0]), "+f"((d)[1]), "+f"((d)[2]), "+f"((d)[3])                \
        : "r"((a)[0]), "r"((a)[1]), "r"((a)[2]), "r"((a)[3]),                   \
          "r"((b)[0]), "r"((b)[1]))

// ---------------------------------------------------------------------------
// Dedup: flag -> prefix scan (deterministic) -> uid maps
// ---------------------------------------------------------------------------
__global__ void dedup_clear_kernel() {
    const int i = blockIdx.x * blockDim.x + threadIdx.x;
    if (i < Vv) g_flag[i] = 0;
}
__global__ void dedup_mark_kernel(const int* __restrict__ docs) {
    const int m = blockIdx.x * blockDim.x + threadIdx.x;
    if (m < Mtot) g_flag[docs[m]] = 1;       // racing writes of 1: benign
}
__global__ void __launch_bounds__(1024) dedup_scan_kernel() {
    __shared__ int ss[1024];
    const int tid = threadIdx.x;
    const int CHUNK = (Vv + 1023) / 1024;    // 49
    const int base = tid * CHUNK;
    int s = 0;
    for (int i = 0; i < CHUNK; i++) {
        const int v = base + i;
        if (v < Vv) s += g_flag[v];
    }
    ss[tid] = s;
    __syncthreads();
    for (int off = 1; off < 1024; off <<= 1) {
        int v = (tid >= off) ? ss[tid - off] : 0;
        __syncthreads();
        ss[tid] += v;
        __syncthreads();
    }
    int run = (tid == 0) ? 0 : ss[tid - 1];
    if (tid == 1023) g_count = ss[1023];
    for (int i = 0; i < CHUNK; i++) {
        const int v = base + i;
        if (v < Vv && g_flag[v]) {
            g_tok[run] = v;
            g_flag[v] = run + 1;             // uid+1 (0 = unused)
            run++;
        }
    }
}
__global__ void dedup_uid_kernel(const int* __restrict__ docs) {
    const int m = blockIdx.x * blockDim.x + threadIdx.x;
    if (m < Mtot) g_uid[m] = g_flag[docs[m]] - 1;
}

// ---------------------------------------------------------------------------
// Conversion: A, B -> fp16
// ---------------------------------------------------------------------------
__global__ void conv_emb_kernel(const float* __restrict__ emb)
{
    const int u = blockIdx.x;
    if (u >= g_count) return;
    const int k = threadIdx.x;          // 0..319
    const int tok = g_tok[u];
    float x = (k < En) ? emb[(size_t)tok * En + k] : 0.0f;
    g_A2[(size_t)u * Kp + k] = __float2half_rn(x);
}

__global__ void conv_diag_kernel(const float* __restrict__ diags)
{
    const int d = blockIdx.x;           // 0..2815
    const int k = threadIdx.x;
    float x = (d < Dn && k < En) ? diags[(size_t)d * En + k] : 0.0f;
    g_B2[(size_t)d * Kp + k] = __float2half_rn(x);
}

// ---------------------------------------------------------------------------
// Kernel 1: fp16 HMMA GEMM over uid rows.  ts_u[u,n] = A2[u]·B2[n] + bias[n]
// Chunk 9 covers k 288..319; cols 304..319 are zero -> ks=1 skipped.
// ---------------------------------------------------------------------------
__global__ void __launch_bounds__(256, 2)
gemm_hmma_kernel(const float* __restrict__ bias)
{
    const int m0 = blockIdx.y * TM;
    const int cnt = g_count;
    if (m0 >= cnt) return;              // uniform per-CTA exit

    extern __shared__ char smem[];
    const uint32_t sbase = s2u(smem);

    const int tid  = threadIdx.x;
    const int wid  = tid >> 5;
    const int lane = tid & 31;
    const int wm   = wid & 3;            // 0..3  (M)
    const int wn   = wid >> 2;           // 0..1  (N)
    const int n0   = blockIdx.x * TN;

    const uint32_t aoff = (uint32_t)((((lane >> 3) & 1) * 8 + (lane & 7)) * ROWB
                                     + ((lane >> 4) * 8) * 2);
    const uint32_t boff = (uint32_t)(((lane >> 4) * 8 + (lane & 7)) * ROWB
                                     + (((lane >> 3) & 1) * 8) * 2);

    const int cr0 = tid >> 2;            // rows 0..63 (+64)
    const int cc  = (tid & 3) * 8;       // fp16 col offset

    auto load_stage = [&](int buf, int kt) {
        const uint32_t sb = sbase + (uint32_t)buf * STAGE;
        const int kk = kt * BK;
        const bool used = (kt != 9) || (cc < 16);   // cols 304+ never consumed
        if (used) {
            #pragma unroll
            for (int u = 0; u < 2; u++) {
                const int r = cr0 + u * 64;
                CP_ASYNC16(sb + (uint32_t)r * ROWB + (uint32_t)(cc * 2),
                           g_A2 + (size_t)(m0 + r) * Kp + kk + cc);
            }
            #pragma unroll
            for (int u = 0; u < 2; u++) {
                const int r = cr0 + u * 64;
                CP_ASYNC16(sb + ASZ + (uint32_t)r * ROWB + (uint32_t)(cc * 2),
                           g_B2 + (size_t)(n0 + r) * Kp + kk + cc);
            }
        }
        CP_COMMIT();
    };

    float c[2][8][4];
    #pragma unroll
    for (int i = 0; i < 2; i++)
        #pragma unroll
        for (int j = 0; j < 8; j++)
            #pragma unroll
            for (int q = 0; q < 4; q++) c[i][j][q] = 0.f;

    load_stage(0, 0);
    load_stage(1, 1);

    for (int kt = 0; kt < NKT; kt++) {
        if (kt < NKT - 1) CP_WAIT(1);
        else              CP_WAIT(0);
        __syncthreads();

        if (kt + 2 < NKT) load_stage((kt + 2) % NSTG, kt + 2);

        const uint32_t sA = sbase + (uint32_t)(kt % NSTG) * STAGE;
        const uint32_t sB = sA + ASZ;

        auto do_ks = [&](int ks) {
            uint32_t a[2][4], bfr[8][2];
            #pragma unroll
            for (int i = 0; i < 2; i++)
                LDSM_X4(a[i], sA + (uint32_t)((wm * 32 + i * 16) * ROWB) + (uint32_t)(ks * 32) + aoff);
            #pragma unroll
            for (int j2 = 0; j2 < 4; j2++)
                LDSM_X4_B(bfr[j2 * 2][0], bfr[j2 * 2][1],
                          bfr[j2 * 2 + 1][0], bfr[j2 * 2 + 1][1],
                          sB + (uint32_t)((wn * 64 + j2 * 16) * ROWB) + (uint32_t)(ks * 32) + boff);
            #pragma unroll
            for (int i = 0; i < 2; i++)
                #pragma unroll
                for (int j = 0; j < 8; j++)
                    MMA_F16(c[i][j], a[i], bfr[j]);
        };

        do_ks(0);
        if (kt != 9) do_ks(1);            // tail chunk: k 304..319 are all zero
    }

    // ---- epilogue: plain [uid][n] store with bias ----
    const int gid = lane >> 2;
    const int tig = lane & 3;
    #pragma unroll
    for (int i = 0; i < 2; i++) {
        const int r0 = m0 + wm * 32 + i * 16 + gid;
        #pragma unroll
        for (int j = 0; j < 8; j++) {
            const int n = n0 + wn * 64 + j * 8 + tig * 2;
            const float bx = __ldg(bias + (n < Dn ? n : 0));
            const float by = __ldg(bias + (n + 1 < Dn ? n + 1 : 0));
            #pragma unroll
            for (int h = 0; h < 2; h++) {
                const int m = r0 + h * 8;
                if (m < cnt) {
                    *reinterpret_cast<float2*>(g_tsu + (size_t)m * Np + n) =
                        make_float2(c[i][j][h * 2] + bx, c[i][j][h * 2 + 1] + by);
                }
            }
        }
    }
}

// ---------------------------------------------------------------------------
// Kernel 2a: chunked max-plus scan; each ts row read ONCE per (b,ch) block
// (all 200 patterns resident in one 256-thread block). Triangular basis.
// Slot layout (64 floats): [0..48] M cols j*7+i, [49..55] C, [56..63] S.
// ---------------------------------------------------------------------------
__global__ void __launch_bounds__(256)
scan_part_kernel(const float* __restrict__ epsilon)
{
    const int b   = blockIdx.x;
    const int ch  = blockIdx.y;
    const int tid = threadIdx.x;

    __shared__ int uids[CL];
    for (int i = tid; i < CL; i += 256)
        uids[i] = g_uid[b * Ln + ch * CL + i];
    __syncthreads();
    if (tid >= Pn) return;
    const int p = tid;

    float e[6];
    #pragma unroll
    for (int j = 0; j < 6; j++) e[j] = __ldg(epsilon + p * 6 + j);

    float h[8][7];
    #pragma unroll
    for (int j = 0; j < 8; j++)
        #pragma unroll
        for (int i = 0; i < 7; i++) h[j][i] = NINF;
    #pragma unroll
    for (int j = 0; j < 7; j++) h[j][j] = 0.0f;
    float smax[8];
    #pragma unroll
    for (int j = 0; j < 8; j++) smax[j] = NINF;

    const int poff = p * 14;

    float2 nxv[7];
    {
        const float* r = g_tsu + (size_t)uids[0] * Np + poff;
        #pragma unroll
        for (int q = 0; q < 7; q++) nxv[q] = *reinterpret_cast<const float2*>(r + 2 * q);
    }

    for (int l = 0; l < CL; l++) {
        float xv[14];
        #pragma unroll
        for (int q = 0; q < 7; q++) { xv[2 * q] = nxv[q].x; xv[2 * q + 1] = nxv[q].y; }
        if (l + 1 < CL) {
            const float* r = g_tsu + (size_t)uids[l + 1] * Np + poff;
            #pragma unroll
            for (int q = 0; q < 7; q++) nxv[q] = *reinterpret_cast<const float2*>(r + 2 * q);
        }

        // basis columns j = 0..6 (triangular: states < j stay NINF)
        #pragma unroll
        for (int j = 0; j < 7; j++) {
            float nh[7];
            float aeprev = h[j][j];                 // ae[j]
            nh[j] = aeprev + xv[j];                 // pure self-loop at state j
            #pragma unroll
            for (int m = j + 1; m < 7; m++) {
                const float aem = fmaxf(h[j][m], h[j][m - 1] + e[m - 1]);
                nh[m] = fmaxf(aeprev + xv[7 + m - 1], aem + xv[m]);
                aeprev = aem;
            }
            smax[j] = fmaxf(smax[j], nh[6]);
            #pragma unroll
            for (int m = j; m < 7; m++) h[j][m] = nh[m];
        }
        // const column (exact reference semantics incl. restart)
        {
            float ae[7];
            ae[0] = fmaxf(h[7][0], NEG);
            #pragma unroll
            for (int m = 1; m < 7; m++) ae[m] = fmaxf(h[7][m], h[7][m - 1] + e[m - 1]);
            float nh[7];
            nh[0] = fmaxf(0.0f, ae[0] + xv[0]);
            #pragma unroll
            for (int m = 1; m < 7; m++)
                nh[m] = fmaxf(ae[m - 1] + xv[7 + m - 1], ae[m] + xv[m]);
            smax[7] = fmaxf(smax[7], nh[6]);
            #pragma unroll
            for (int m = 0; m < 7; m++) h[7][m] = nh[m];
        }
    }

    float* slot = g_part + ((size_t)(b * Pn + p) * NCH + ch) * 64;
    #pragma unroll
    for (int j = 0; j < 7; j++)
        #pragma unroll
        for (int i = 0; i < 7; i++) slot[j * 7 + i] = (i >= j) ? h[j][i] : NINF;
    #pragma unroll
    for (int i = 0; i < 7; i++) slot[49 + i] = h[7][i];
    #pragma unroll
    for (int j = 0; j < 8; j++) slot[56 + j] = smax[j];
}

// ---------------------------------------------------------------------------
// Kernel 2b: combine the NCH chunk transforms per chain.
// ---------------------------------------------------------------------------
__global__ void scan_combine_kernel()
{
    const int bp = blockIdx.x * blockDim.x + threadIdx.x;
    if (bp >= Bn * Pn) return;

    float h[7];
    h[0] = 0.0f;
    #pragma unroll
    for (int i = 1; i < 7; i++) h[i] = NEG;
    float s = NEG;

    #pragma unroll 1
    for (int c = 0; c < NCH; c++) {
        const float* sl = g_part + ((size_t)bp * NCH + c) * 64;
        float ns = fmaxf(s, sl[63]);
        #pragma unroll
        for (int j = 0; j < 7; j++) ns = fmaxf(ns, sl[56 + j] + h[j]);
        float nh[7];
        #pragma unroll
        for (int i = 0; i < 7; i++) {
            float v = sl[49 + i];
            #pragma unroll
            for (int j = 0; j < 7; j++) v = fmaxf(v, sl[j * 7 + i] + h[j]);
            nh[i] = v;
        }
        #pragma unroll
        for (int i = 0; i < 7; i++) h[i] = nh[i];
        s = ns;
    }
    g_scores[bp] = s;
}

// ---------------------------------------------------------------------------
// Kernel 3: MLP + log_softmax. One block per batch row.
// ---------------------------------------------------------------------------
__global__ void mlp_kernel(const float* __restrict__ w1, const float* __restrict__ b1,
                           const float* __restrict__ w2, const float* __restrict__ b2,
                           const float* __restrict__ w3, const float* __restrict__ b3,
                           float* __restrict__ out)
{
    const int b = blockIdx.x;
    const int tid = threadIdx.x;
    __shared__ float sc[Pn];
    __shared__ float h1[Hn];
    __shared__ float h2[Hn];

    for (int i = tid; i < Pn; i += blockDim.x) sc[i] = g_scores[b * Pn + i];
    __syncthreads();

    if (tid < Hn) {
        float acc = b1[tid];
        #pragma unroll 4
        for (int p = 0; p < Pn; p++) acc = fmaf(sc[p], w1[p * Hn + tid], acc);
        h1[tid] = fmaxf(acc, 0.f);
    }
    __syncthreads();

    if (tid < Hn) {
        float acc = b2[tid];
        #pragma unroll 4
        for (int j = 0; j < Hn; j++) acc = fmaf(h1[j], w2[j * Hn + tid], acc);
        h2[tid] = fmaxf(acc, 0.f);
    }
    __syncthreads();

    if (tid == 0) {
        float l0 = b3[0], l1 = b3[1];
        for (int j = 0; j < Hn; j++) {
            l0 = fmaf(h2[j], w3[j * 2 + 0], l0);
            l1 = fmaf(h2[j], w3[j * 2 + 1], l1);
        }
        float mx  = fmaxf(l0, l1);
        float lse = mx + logf(expf(l0 - mx) + expf(l1 - mx));
        out[b * 2 + 0] = l0 - lse;
        out[b * 2 + 1] = l1 - lse;
    }
}

// ---------------------------------------------------------------------------
extern "C" void kernel_launch(void* const* d_in, const int* in_sizes, int n_in,
                              void* d_out, int out_size)
{
    const int*   docs    = (const int*)  d_in[0];
    const float* emb     = (const float*)d_in[1];
    const float* diags   = (const float*)d_in[2];
    const float* bias    = (const float*)d_in[3];
    const float* epsilon = (const float*)d_in[4];
    const float* w1      = (const float*)d_in[5];
    const float* b1      = (const float*)d_in[6];
    const float* w2      = (const float*)d_in[7];
    const float* b2      = (const float*)d_in[8];
    const float* w3      = (const float*)d_in[9];
    const float* b3      = (const float*)d_in[10];
    float* out = (float*)d_out;

    cudaFuncSetAttribute(gemm_hmma_kernel,
                         cudaFuncAttributeMaxDynamicSharedMemorySize, SMEM_DYN);

    dedup_clear_kernel<<<(Vv + 255) / 256, 256>>>();
    dedup_mark_kernel<<<(Mtot + 255) / 256, 256>>>(docs);
    dedup_scan_kernel<<<1, 1024>>>();
    dedup_uid_kernel<<<(Mtot + 255) / 256, 256>>>(docs);

    conv_emb_kernel<<<Mtot, Kp>>>(emb);
    conv_diag_kernel<<<Np, Kp>>>(diags);

    dim3 gridG(Np / TN, Mtot / TM);   // (22, 256); CTAs beyond count exit
    gemm_hmma_kernel<<<gridG, 256, SMEM_DYN>>>(bias);

    dim3 gridS(Bn, NCH);              // (64, 4)
    scan_part_kernel<<<gridS, 256>>>(epsilon);
    scan_combine_kernel<<<(Bn * Pn + 127) / 128, 128>>>();

    mlp_kernel<<<Bn, 128>>>(w1, b1, w2, b2, w3, b3, out);
}

// round 14
// speedup vs baseline: 2.3747x; 1.0063x over previous
#include <cuda_runtime.h>
#include <cuda_bf16.h>
#include <cuda_fp16.h>
#include <math.h>
#include <stdint.h>

// Problem constants
#define Bn   64
#define Ln   512
#define En   300
#define Vv   50000
#define Pn   200
#define Dn   2800          // P * 2 * M
#define Hn   100
#define Mtot (Bn * Ln)     // 32768
#define NEG  (-100.0f)
#define NINF (-1.0e30f)

// GEMM config: plain fp16 GEMM, K padded 300->320.
#define Kp    320
#define Np    2816
#define TM    128
#define TN    128
#define BK    32                 // fp16 per k-tile
#define NKT   10                 // 10 chunks (chunk 9: ks=0 only; k 304+ zero)
#define ROWB  80u                // padded smem row stride (bytes) per 32-fp16 row
#define ASZ   (128u * ROWB)      // 10240
#define STAGE (2u * ASZ)         // A + B = 20480
#define NSTG  3
#define SMEM_DYN (NSTG * STAGE)  // 61440

// Scan split config
#define NCH   4
#define CL    (Ln / NCH)         // 128

// Scratch (static device globals — no dynamic allocation)
__device__ __align__(256) __half g_tsu[(size_t)Mtot * Np];  // [uid][n] fp16
__device__ __align__(256) float  g_part[(size_t)Bn * Pn * NCH * 64];
__device__ __align__(256) __half g_A2[(size_t)Mtot * Kp];   // fp16(a)
__device__ __align__(256) __half g_B2[(size_t)Np * Kp];     // fp16(b)
__device__ int g_flag[Vv];
__device__ int g_tok[Mtot];
__device__ int g_uid[Mtot];
__device__ int g_count;

// ---------------------------------------------------------------------------
// PTX helpers (baseline PTX only — no 'a'-target instructions)
// ---------------------------------------------------------------------------
__device__ __forceinline__ uint32_t s2u(const void* p) {
    uint32_t a;
    asm("{ .reg .u64 t; cvta.to.shared.u64 t, %1; cvt.u32.u64 %0, t; }"
        : "=r"(a) : "l"(p));
    return a;
}

#define CP_ASYNC16(dst, src) \
    asm volatile("cp.async.cg.shared.global [%0], [%1], 16;" :: "r"(dst), "l"(src) : "memory")
#define CP_COMMIT() asm volatile("cp.async.commit_group;" ::: "memory")
#define CP_WAIT(n)  asm volatile("cp.async.wait_group %0;" :: "n"(n) : "memory")

#define LDSM_X4(r, addr)                                                        \
    asm volatile("ldmatrix.sync.aligned.m8n8.x4.shared.b16 {%0,%1,%2,%3}, [%4];" \
        : "=r"((r)[0]), "=r"((r)[1]), "=r"((r)[2]), "=r"((r)[3]) : "r"(addr))

#define LDSM_X4_B(r0, r1, r2, r3, addr)                                         \
    asm volatile("ldmatrix.sync.aligned.m8n8.x4.shared.b16 {%0,%1,%2,%3}, [%4];" \
        : "=r"(r0), "=r"(r1), "=r"(r2), "=r"(r3) : "r"(addr))

#define MMA_F16(d, a, b)                                                        \
    asm volatile("mma.sync.aligned.m16n8k16.row.col.f32.f16.f16.f32 "           \
        "{%0,%1,%2,%3}, {%4,%5,%6,%7}, {%8,%9}, {%0,%1,%2,%3};"                 \
        : "+f"((d)[0]), "+f"((d)[1]), "+f"((d)[2]), "+f"((d)[3])                \
        : "r"((a)[0]), "r"((a)[1]), "r"((a)[2]), "r"((a)[3]),                   \
          "r"((b)[0]), "r"((b)[1]))

// ---------------------------------------------------------------------------
// Dedup: flag -> prefix scan (deterministic) -> uid maps
// ---------------------------------------------------------------------------
__global__ void dedup_clear_kernel() {
    const int i = blockIdx.x * blockDim.x + threadIdx.x;
    if (i < Vv) g_flag[i] = 0;
}
__global__ void dedup_mark_kernel(const int* __restrict__ docs) {
    const int m = blockIdx.x * blockDim.x + threadIdx.x;
    if (m < Mtot) g_flag[docs[m]] = 1;       // racing writes of 1: benign
}
__global__ void __launch_bounds__(1024) dedup_scan_kernel() {
    __shared__ int ss[1024];
    const int tid = threadIdx.x;
    const int CHUNK = (Vv + 1023) / 1024;    // 49
    const int base = tid * CHUNK;
    int s = 0;
    for (int i = 0; i < CHUNK; i++) {
        const int v = base + i;
        if (v < Vv) s += g_flag[v];
    }
    ss[tid] = s;
    __syncthreads();
    for (int off = 1; off < 1024; off <<= 1) {
        int v = (tid >= off) ? ss[tid - off] : 0;
        __syncthreads();
        ss[tid] += v;
        __syncthreads();
    }
    int run = (tid == 0) ? 0 : ss[tid - 1];
    if (tid == 1023) g_count = ss[1023];
    for (int i = 0; i < CHUNK; i++) {
        const int v = base + i;
        if (v < Vv && g_flag[v]) {
            g_tok[run] = v;
            g_flag[v] = run + 1;             // uid+1 (0 = unused)
            run++;
        }
    }
}
__global__ void dedup_uid_kernel(const int* __restrict__ docs) {
    const int m = blockIdx.x * blockDim.x + threadIdx.x;
    if (m < Mtot) g_uid[m] = g_flag[docs[m]] - 1;
}

// ---------------------------------------------------------------------------
// Conversion: A, B -> fp16
// ---------------------------------------------------------------------------
__global__ void conv_emb_kernel(const float* __restrict__ emb)
{
    const int u = blockIdx.x;
    if (u >= g_count) return;
    const int k = threadIdx.x;          // 0..319
    const int tok = g_tok[u];
    float x = (k < En) ? emb[(size_t)tok * En + k] : 0.0f;
    g_A2[(size_t)u * Kp + k] = __float2half_rn(x);
}

__global__ void conv_diag_kernel(const float* __restrict__ diags)
{
    const int d = blockIdx.x;           // 0..2815
    const int k = threadIdx.x;
    float x = (d < Dn && k < En) ? diags[(size_t)d * En + k] : 0.0f;
    g_B2[(size_t)d * Kp + k] = __float2half_rn(x);
}

// ---------------------------------------------------------------------------
// Kernel 1: fp16 HMMA GEMM over uid rows.  ts_u[u,n] = A2[u]·B2[n] + bias[n]
// Chunk 9 covers k 288..319; cols 304..319 are zero -> ks=1 skipped.
// ---------------------------------------------------------------------------
__global__ void __launch_bounds__(256, 2)
gemm_hmma_kernel(const float* __restrict__ bias)
{
    const int m0 = blockIdx.y * TM;
    const int cnt = g_count;
    if (m0 >= cnt) return;              // uniform per-CTA exit

    extern __shared__ char smem[];
    const uint32_t sbase = s2u(smem);

    const int tid  = threadIdx.x;
    const int wid  = tid >> 5;
    const int lane = tid & 31;
    const int wm   = wid & 3;            // 0..3  (M)
    const int wn   = wid >> 2;           // 0..1  (N)
    const int n0   = blockIdx.x * TN;

    const uint32_t aoff = (uint32_t)((((lane >> 3) & 1) * 8 + (lane & 7)) * ROWB
                                     + ((lane >> 4) * 8) * 2);
    const uint32_t boff = (uint32_t)(((lane >> 4) * 8 + (lane & 7)) * ROWB
                                     + (((lane >> 3) & 1) * 8) * 2);

    const int cr0 = tid >> 2;            // rows 0..63 (+64)
    const int cc  = (tid & 3) * 8;       // fp16 col offset

    auto load_stage = [&](int buf, int kt) {
        const uint32_t sb = sbase + (uint32_t)buf * STAGE;
        const int kk = kt * BK;
        const bool used = (kt != 9) || (cc < 16);   // cols 304+ never consumed
        if (used) {
            #pragma unroll
            for (int u = 0; u < 2; u++) {
                const int r = cr0 + u * 64;
                CP_ASYNC16(sb + (uint32_t)r * ROWB + (uint32_t)(cc * 2),
                           g_A2 + (size_t)(m0 + r) * Kp + kk + cc);
            }
            #pragma unroll
            for (int u = 0; u < 2; u++) {
                const int r = cr0 + u * 64;
                CP_ASYNC16(sb + ASZ + (uint32_t)r * ROWB + (uint32_t)(cc * 2),
                           g_B2 + (size_t)(n0 + r) * Kp + kk + cc);
            }
        }
        CP_COMMIT();
    };

    float c[2][8][4];
    #pragma unroll
    for (int i = 0; i < 2; i++)
        #pragma unroll
        for (int j = 0; j < 8; j++)
            #pragma unroll
            for (int q = 0; q < 4; q++) c[i][j][q] = 0.f;

    load_stage(0, 0);
    load_stage(1, 1);

    for (int kt = 0; kt < NKT; kt++) {
        if (kt < NKT - 1) CP_WAIT(1);
        else              CP_WAIT(0);
        __syncthreads();

        if (kt + 2 < NKT) load_stage((kt + 2) % NSTG, kt + 2);

        const uint32_t sA = sbase + (uint32_t)(kt % NSTG) * STAGE;
        const uint32_t sB = sA + ASZ;

        auto do_ks = [&](int ks) {
            uint32_t a[2][4], bfr[8][2];
            #pragma unroll
            for (int i = 0; i < 2; i++)
                LDSM_X4(a[i], sA + (uint32_t)((wm * 32 + i * 16) * ROWB) + (uint32_t)(ks * 32) + aoff);
            #pragma unroll
            for (int j2 = 0; j2 < 4; j2++)
                LDSM_X4_B(bfr[j2 * 2][0], bfr[j2 * 2][1],
                          bfr[j2 * 2 + 1][0], bfr[j2 * 2 + 1][1],
                          sB + (uint32_t)((wn * 64 + j2 * 16) * ROWB) + (uint32_t)(ks * 32) + boff);
            #pragma unroll
            for (int i = 0; i < 2; i++)
                #pragma unroll
                for (int j = 0; j < 8; j++)
                    MMA_F16(c[i][j], a[i], bfr[j]);
        };

        do_ks(0);
        if (kt != 9) do_ks(1);            // tail chunk: k 304..319 are all zero
    }

    // ---- epilogue: fp16 [uid][n] store with bias ----
    const int gid = lane >> 2;
    const int tig = lane & 3;
    #pragma unroll
    for (int i = 0; i < 2; i++) {
        const int r0 = m0 + wm * 32 + i * 16 + gid;
        #pragma unroll
        for (int j = 0; j < 8; j++) {
            const int n = n0 + wn * 64 + j * 8 + tig * 2;
            const float bx = __ldg(bias + (n < Dn ? n : 0));
            const float by = __ldg(bias + (n + 1 < Dn ? n + 1 : 0));
            #pragma unroll
            for (int h = 0; h < 2; h++) {
                const int m = r0 + h * 8;
                if (m < cnt) {
                    __half2 v = __floats2half2_rn(c[i][j][h * 2] + bx,
                                                  c[i][j][h * 2 + 1] + by);
                    *reinterpret_cast<__half2*>(g_tsu + (size_t)m * Np + n) = v;
                }
            }
        }
    }
}

// ---------------------------------------------------------------------------
// Kernel 2: chunked max-plus scan; each ts row read ONCE per (b,ch) block
// (all 200 patterns resident in one 256-thread block). Triangular basis.
// Slot layout (64 floats): [0..48] M cols j*7+i, [49..55] C, [56..63] S.
// ---------------------------------------------------------------------------
__global__ void __launch_bounds__(256)
scan_part_kernel(const float* __restrict__ epsilon)
{
    const int b   = blockIdx.x;
    const int ch  = blockIdx.y;
    const int tid = threadIdx.x;

    __shared__ int uids[CL];
    for (int i = tid; i < CL; i += 256)
        uids[i] = g_uid[b * Ln + ch * CL + i];
    __syncthreads();
    if (tid >= Pn) return;
    const int p = tid;

    float e[6];
    #pragma unroll
    for (int j = 0; j < 6; j++) e[j] = __ldg(epsilon + p * 6 + j);

    float h[8][7];
    #pragma unroll
    for (int j = 0; j < 8; j++)
        #pragma unroll
        for (int i = 0; i < 7; i++) h[j][i] = NINF;
    #pragma unroll
    for (int j = 0; j < 7; j++) h[j][j] = 0.0f;
    float smax[8];
    #pragma unroll
    for (int j = 0; j < 8; j++) smax[j] = NINF;

    const int poff7 = p * 7;   // half2 units

    float2 nxv[7];
    {
        const __half2* r = reinterpret_cast<const __half2*>(
            g_tsu + (size_t)uids[0] * Np) + poff7;
        #pragma unroll
        for (int q = 0; q < 7; q++) nxv[q] = __half22float2(r[q]);
    }

    for (int l = 0; l < CL; l++) {
        float xv[14];
        #pragma unroll
        for (int q = 0; q < 7; q++) { xv[2 * q] = nxv[q].x; xv[2 * q + 1] = nxv[q].y; }
        if (l + 1 < CL) {
            const __half2* r = reinterpret_cast<const __half2*>(
                g_tsu + (size_t)uids[l + 1] * Np) + poff7;
            #pragma unroll
            for (int q = 0; q < 7; q++) nxv[q] = __half22float2(r[q]);
        }

        // basis columns j = 0..6 (triangular: states < j stay NINF)
        #pragma unroll
        for (int j = 0; j < 7; j++) {
            float nh[7];
            float aeprev = h[j][j];                 // ae[j]
            nh[j] = aeprev + xv[j];                 // pure self-loop at state j
            #pragma unroll
            for (int m = j + 1; m < 7; m++) {
                const float aem = fmaxf(h[j][m], h[j][m - 1] + e[m - 1]);
                nh[m] = fmaxf(aeprev + xv[7 + m - 1], aem + xv[m]);
                aeprev = aem;
            }
            smax[j] = fmaxf(smax[j], nh[6]);
            #pragma unroll
            for (int m = j; m < 7; m++) h[j][m] = nh[m];
        }
        // const column (exact reference semantics incl. restart)
        {
            float ae[7];
            ae[0] = fmaxf(h[7][0], NEG);
            #pragma unroll
            for (int m = 1; m < 7; m++) ae[m] = fmaxf(h[7][m], h[7][m - 1] + e[m - 1]);
            float nh[7];
            nh[0] = fmaxf(0.0f, ae[0] + xv[0]);
            #pragma unroll
            for (int m = 1; m < 7; m++)
                nh[m] = fmaxf(ae[m - 1] + xv[7 + m - 1], ae[m] + xv[m]);
            smax[7] = fmaxf(smax[7], nh[6]);
            #pragma unroll
            for (int m = 0; m < 7; m++) h[7][m] = nh[m];
        }
    }

    float* slot = g_part + ((size_t)(b * Pn + p) * NCH + ch) * 64;
    #pragma unroll
    for (int j = 0; j < 7; j++)
        #pragma unroll
        for (int i = 0; i < 7; i++) slot[j * 7 + i] = (i >= j) ? h[j][i] : NINF;
    #pragma unroll
    for (int i = 0; i < 7; i++) slot[49 + i] = h[7][i];
    #pragma unroll
    for (int j = 0; j < 8; j++) slot[56 + j] = smax[j];
}

// ---------------------------------------------------------------------------
// Kernel 3: fused combine + MLP + log_softmax. One block per batch row.
// Threads 0..199 fold the NCH chunk transforms into sc[p], then MLP.
// ---------------------------------------------------------------------------
__global__ void __launch_bounds__(256)
mlp_kernel(const float* __restrict__ w1, const float* __restrict__ b1,
           const float* __restrict__ w2, const float* __restrict__ b2,
           const float* __restrict__ w3, const float* __restrict__ b3,
           float* __restrict__ out)
{
    const int b = blockIdx.x;
    const int tid = threadIdx.x;
    __shared__ float sc[Pn];
    __shared__ float h1[Hn];
    __shared__ float h2[Hn];

    if (tid < Pn) {
        float h[7];
        h[0] = 0.0f;
        #pragma unroll
        for (int i = 1; i < 7; i++) h[i] = NEG;
        float s = NEG;
        #pragma unroll 1
        for (int c = 0; c < NCH; c++) {
            const float* sl = g_part + ((size_t)(b * Pn + tid) * NCH + c) * 64;
            float ns = fmaxf(s, sl[63]);
            #pragma unroll
            for (int j = 0; j < 7; j++) ns = fmaxf(ns, sl[56 + j] + h[j]);
            float nh[7];
            #pragma unroll
            for (int i = 0; i < 7; i++) {
                float v = sl[49 + i];
                #pragma unroll
                for (int j = 0; j < 7; j++) v = fmaxf(v, sl[j * 7 + i] + h[j]);
                nh[i] = v;
            }
            #pragma unroll
            for (int i = 0; i < 7; i++) h[i] = nh[i];
            s = ns;
        }
        sc[tid] = s;
    }
    __syncthreads();

    if (tid < Hn) {
        float acc = b1[tid];
        #pragma unroll 4
        for (int p = 0; p < Pn; p++) acc = fmaf(sc[p], w1[p * Hn + tid], acc);
        h1[tid] = fmaxf(acc, 0.f);
    }
    __syncthreads();

    if (tid < Hn) {
        float acc = b2[tid];
        #pragma unroll 4
        for (int j = 0; j < Hn; j++) acc = fmaf(h1[j], w2[j * Hn + tid], acc);
        h2[tid] = fmaxf(acc, 0.f);
    }
    __syncthreads();

    if (tid == 0) {
        float l0 = b3[0], l1 = b3[1];
        for (int j = 0; j < Hn; j++) {
            l0 = fmaf(h2[j], w3[j * 2 + 0], l0);
            l1 = fmaf(h2[j], w3[j * 2 + 1], l1);
        }
        float mx  = fmaxf(l0, l1);
        float lse = mx + logf(expf(l0 - mx) + expf(l1 - mx));
        out[b * 2 + 0] = l0 - lse;
        out[b * 2 + 1] = l1 - lse;
    }
}

// ---------------------------------------------------------------------------
extern "C" void kernel_launch(void* const* d_in, const int* in_sizes, int n_in,
                              void* d_out, int out_size)
{
    const int*   docs    = (const int*)  d_in[0];
    const float* emb     = (const float*)d_in[1];
    const float* diags   = (const float*)d_in[2];
    const float* bias    = (const float*)d_in[3];
    const float* epsilon = (const float*)d_in[4];
    const float* w1      = (const float*)d_in[5];
    const float* b1      = (const float*)d_in[6];
    const float* w2      = (const float*)d_in[7];
    const float* b2      = (const float*)d_in[8];
    const float* w3      = (const float*)d_in[9];
    const float* b3      = (const float*)d_in[10];
    float* out = (float*)d_out;

    cudaFuncSetAttribute(gemm_hmma_kernel,
                         cudaFuncAttributeMaxDynamicSharedMemorySize, SMEM_DYN);

    dedup_clear_kernel<<<(Vv + 255) / 256, 256>>>();
    dedup_mark_kernel<<<(Mtot + 255) / 256, 256>>>(docs);
    dedup_scan_kernel<<<1, 1024>>>();
    dedup_uid_kernel<<<(Mtot + 255) / 256, 256>>>(docs);

    conv_emb_kernel<<<Mtot, Kp>>>(emb);
    conv_diag_kernel<<<Np, Kp>>>(diags);

    dim3 gridG(Np / TN, Mtot / TM);   // (22, 256); CTAs beyond count exit
    gemm_hmma_kernel<<<gridG, 256, SMEM_DYN>>>(bias);

    dim3 gridS(Bn, NCH);              // (64, 4)
    scan_part_kernel<<<gridS, 256>>>(epsilon);

    mlp_kernel<<<Bn, 256>>>(w1, b1, w2, b2, w3, b3, out);
}